// round 5
// baseline (speedup 1.0000x reference)
#include <cuda_runtime.h>
#include <cuda_fp16.h>
#include <math.h>
#include <stdint.h>

#define NT    256
#define RB    64
#define AST   264            // A tile k-stride (fp16): 256 + 8 pad
#define WST   40             // W panel k-stride (fp16): 32 + 8 pad
#define RSTR  193

// ---- smem layout (bytes) ----
#define OFF_A       0                   // 64*264*2 = 33792 fp16
#define OFF_WP      33792               // 2 stages * 20480
#define SLOT_B      20480
#define OFF_W0S     54272               // transient: inside WP stage 1 (8192 B)
#define OFF_B1S     74752               // 256 f32
#define OFF_BOS     75776               // 192 f32
#define OFF_B0S     76544               // 256 f32
#define SMEM_BYTES  77568
// raw buffer (epilogue2): 64*193*4 = 49408 at sm[0], overlaps A+WP stage0 (dead then)

#define PAN1_B 20480                    // 256*40*2
#define PAN2_B 15360                    // 192*40*2

// ---- prebuilt fp16 weight panels ----
__device__ __align__(16) __half g_w1[8 * 256 * 40];
__device__ __align__(16) __half g_wo[8 * 192 * 40];

// ---- helpers ----
__device__ __forceinline__ uint32_t smem_u32(const void* p) {
    uint32_t a;
    asm("{ .reg .u64 t; cvta.to.shared.u64 t, %1; cvt.u32.u64 %0, t; }" : "=r"(a) : "l"(p));
    return a;
}
__device__ __forceinline__ void cp16(uint32_t dst, const void* src) {
    asm volatile("cp.async.cg.shared.global [%0], [%1], 16;" :: "r"(dst), "l"(src));
}
#define CP_COMMIT() asm volatile("cp.async.commit_group;")
#define CP_WAIT0()  asm volatile("cp.async.wait_group 0;")

__device__ __forceinline__ void mma16(float* d, uint32_t a0, uint32_t a1, uint32_t a2, uint32_t a3,
                                      uint32_t b0, uint32_t b1) {
    asm volatile("mma.sync.aligned.m16n8k16.row.col.f32.f16.f16.f32 "
                 "{%0,%1,%2,%3}, {%4,%5,%6,%7}, {%8,%9}, {%0,%1,%2,%3};"
                 : "+f"(d[0]), "+f"(d[1]), "+f"(d[2]), "+f"(d[3])
                 : "r"(a0), "r"(a1), "r"(a2), "r"(a3), "r"(b0), "r"(b1));
}

__device__ __forceinline__ float softplusf(float v) {
    return fmaxf(v, 0.0f) + log1pf(expf(-fabsf(v)));
}

// 1-product k-panel compute (K=32): d += A * W
template<int NTILES>
__device__ __forceinline__ void panel_compute(const char* A, const char* W,
                                              int akbase, int nbase, int mrow, int qr, int qc,
                                              float d[2][8][4])
{
    #pragma unroll
    for (int ks = 0; ks < 2; ks++) {
        const int kA = akbase + ks * 16 + qc;
        const int kW = ks * 16 + qc;
        uint32_t a[2][4];
        #pragma unroll
        for (int mt = 0; mt < 2; mt++) {
            const uint32_t* ap = (const uint32_t*)(A + ((mrow + mt * 16 + qr) * AST + kA) * 2);
            a[mt][0] = ap[0];
            a[mt][1] = ap[4 * AST];          // +8 rows
            a[mt][2] = ap[4];                // +8 k
            a[mt][3] = ap[4 * AST + 4];
        }
        #pragma unroll
        for (int nt = 0; nt < NTILES; nt++) {
            const uint32_t* bp = (const uint32_t*)(W + ((nbase + nt * 8 + qr) * WST + kW) * 2);
            uint32_t b0 = bp[0], b1 = bp[4];
            #pragma unroll
            for (int mt = 0; mt < 2; mt++)
                mma16(d[mt][nt], a[mt][0], a[mt][1], a[mt][2], a[mt][3], b0, b1);
        }
    }
}

// ---- prep kernels ----
__global__ void prep_w1(const float* __restrict__ W1) {
    int idx = blockIdx.x * blockDim.x + threadIdx.x;      // 81920
    int p = idx / 10240, rem = idx % 10240;
    int n = rem / 40, kk = rem % 40;
    float w = (kk < 32) ? W1[(p * 32 + kk) * 256 + n] : 0.0f;
    g_w1[idx] = __float2half_rn(w);
}
__global__ void prep_wo(const float* __restrict__ Wout) {
    int idx = blockIdx.x * blockDim.x + threadIdx.x;      // 61440
    int p = idx / 7680, rem = idx % 7680;
    int n = rem / 40, kk = rem % 40;
    float w = (kk < 32 && n < 184) ? Wout[(p * 32 + kk) * 184 + n] : 0.0f;
    g_wo[idx] = __float2half_rn(w);
}

// ---- main kernel ----
__global__ void __launch_bounds__(NT, 2)
coupling_hmma_kernel(const float* __restrict__ x,
                     const float* __restrict__ W0,
                     const float* __restrict__ b0,
                     const float* __restrict__ b1,
                     const float* __restrict__ bout,
                     float* __restrict__ out,
                     int B)
{
    extern __shared__ char sm[];
    const int tid = threadIdx.x;
    const int wid = tid >> 5, lane = tid & 31;
    const int mw = wid & 1, nw = wid >> 1;
    const int qr = lane >> 2, qc = (lane & 3) * 2;
    const int row0 = blockIdx.x * RB;
    const uint32_t wp_u32 = smem_u32(sm + OFF_WP);

    float* b0s = (float*)(sm + OFF_B0S);
    float* b1s = (float*)(sm + OFF_B1S);
    float* bos = (float*)(sm + OFF_BOS);
    float* W0s = (float*)(sm + OFF_W0S);

    // ---- prefetch first W1 panel into stage 0 (overlaps GEMM0) ----
    for (int i = tid; i < PAN1_B / 16; i += NT)
        cp16(wp_u32 + i * 16, (const char*)g_w1 + i * 16);
    CP_COMMIT();

    // ---- prologue constants (W0s lives in WP stage-1 slot, consumed before it's used) ----
    for (int i = tid; i < 256; i += NT) { b0s[i] = b0[i]; b1s[i] = b1[i]; }
    for (int i = tid; i < 192; i += NT) bos[i] = (i < 184) ? bout[i] : 0.0f;
    for (int i = tid; i < 2048; i += NT) W0s[i] = W0[i];
    __syncthreads();

    // ---- GEMM0 (exact fp32 FFMA): h0 = relu(x2 @ W0 + b0) -> fp16 A tile ----
    {
        const int r = tid >> 2, q = tid & 3;
        const int cb = q * 64;
        const float4* xp = (const float4*)(x + (size_t)(row0 + r) * 16);
        float4 xc = xp[2], xd = xp[3];
        float xv[8] = {xc.x, xc.y, xc.z, xc.w, xd.x, xd.y, xd.z, xd.w};
        for (int c = 0; c < 64; c += 2) {
            float s0 = b0s[cb + c], s1 = b0s[cb + c + 1];
            #pragma unroll
            for (int j = 0; j < 8; j++) {
                s0 = fmaf(xv[j], W0s[j * 256 + cb + c], s0);
                s1 = fmaf(xv[j], W0s[j * 256 + cb + c + 1], s1);
            }
            s0 = fmaxf(s0, 0.0f); s1 = fmaxf(s1, 0.0f);
            *(__half2*)(sm + OFF_A + ((size_t)r * AST + cb + c) * 2) = __floats2half2_rn(s0, s1);
        }
    }
    __syncthreads();

    float d[2][8][4];
    #pragma unroll
    for (int mt = 0; mt < 2; mt++)
        #pragma unroll
        for (int nt = 0; nt < 8; nt++)
            #pragma unroll
            for (int i = 0; i < 4; i++) d[mt][nt][i] = 0.0f;

    // ---- panel pipeline: p 0..7 = GEMM1 (W1), p 8..15 = GEMM2 (Wout) ----
    for (int p = 0; p < 16; p++) {
        CP_WAIT0();
        __syncthreads();

        if (p == 8) {
            // epilogue1: h1 = relu(d + b1) -> fp16 A tile
            #pragma unroll
            for (int mt = 0; mt < 2; mt++) {
                const int r0 = mw * 32 + mt * 16 + qr;
                #pragma unroll
                for (int nt = 0; nt < 8; nt++) {
                    const int c = nw * 64 + nt * 8 + qc;
                    const float g0 = b1s[c], g1 = b1s[c + 1];
                    float v00 = fmaxf(d[mt][nt][0] + g0, 0.f);
                    float v01 = fmaxf(d[mt][nt][1] + g1, 0.f);
                    float v10 = fmaxf(d[mt][nt][2] + g0, 0.f);
                    float v11 = fmaxf(d[mt][nt][3] + g1, 0.f);
                    *(__half2*)(sm + OFF_A + ((size_t)r0 * AST + c) * 2) = __floats2half2_rn(v00, v01);
                    *(__half2*)(sm + OFF_A + ((size_t)(r0 + 8) * AST + c) * 2) = __floats2half2_rn(v10, v11);
                    #pragma unroll
                    for (int i = 0; i < 4; i++) d[mt][nt][i] = 0.0f;
                }
            }
            __syncthreads();
        }

        // issue(p+1) into the other stage (its previous contents consumed last iter)
        if (p + 1 < 16) {
            const int np = p + 1;
            uint32_t dst = wp_u32 + (np & 1) * SLOT_B;
            if (np < 8) {
                const char* src = (const char*)g_w1 + (size_t)np * PAN1_B;
                for (int i = tid; i < PAN1_B / 16; i += NT) cp16(dst + i * 16, src + i * 16);
            } else {
                const char* src = (const char*)g_wo + (size_t)(np - 8) * PAN2_B;
                for (int i = tid; i < PAN2_B / 16; i += NT) cp16(dst + i * 16, src + i * 16);
            }
            CP_COMMIT();
        } else {
            CP_COMMIT();
        }

        const char* wb = sm + OFF_WP + (p & 1) * SLOT_B;
        if (p < 8)
            panel_compute<8>(sm + OFF_A, wb, p * 32, nw * 64, mw * 32, qr, qc, d);
        else
            panel_compute<6>(sm + OFF_A, wb, (p - 8) * 32, nw * 48, mw * 32, qr, qc, d);
    }
    __syncthreads();   // all GEMM2 A/W reads done

    // ---- epilogue2: raw = d + bout -> smem f32 [64][193] (overlaps A+WP) ----
    float* rawS = (float*)sm;
    #pragma unroll
    for (int mt = 0; mt < 2; mt++) {
        const int r0 = mw * 32 + mt * 16 + qr;
        #pragma unroll
        for (int nt = 0; nt < 6; nt++) {
            const int c = nw * 48 + nt * 8 + qc;
            rawS[r0 * RSTR + c]           = d[mt][nt][0] + bos[c];
            rawS[r0 * RSTR + c + 1]       = d[mt][nt][1] + bos[c + 1];
            rawS[(r0 + 8) * RSTR + c]     = d[mt][nt][2] + bos[c];
            rawS[(r0 + 8) * RSTR + c + 1] = d[mt][nt][3] + bos[c + 1];
        }
    }
    __syncthreads();

    // ---- spline: 4 threads/row, 2 transforms each ----
    {
        const int r = tid >> 2;
        const int q = tid & 3;
        const int ts = q * 2;
        const size_t grow = (size_t)(row0 + r) * 16;
        const float2 x1p = *(const float2*)(x + grow + ts);
        const float x1v[2] = {x1p.x, x1p.y};
        const float CNST = logf(expf(1.0f - 1e-4f) - 1.0f);
        float yv[2];
        float ldsum = 0.0f;

        #pragma unroll 1
        for (int tt = 0; tt < 2; tt++) {
            const float* raw = rawS + r * RSTR + (ts + tt) * 23;
            const float xv = x1v[tt];

            float rw[8], rh[8];
            #pragma unroll
            for (int c = 0; c < 8; c++) { rw[c] = raw[c]; rh[c] = raw[8 + c]; }

            float m = rw[0];
            #pragma unroll
            for (int c = 1; c < 8; c++) m = fmaxf(m, rw[c]);
            float sum = 0.0f, ew[8];
            #pragma unroll
            for (int c = 0; c < 8; c++) { ew[c] = expf(rw[c] - m); sum += ew[c]; }
            float inv = 1.0f / sum;
            float wdt[8];
            #pragma unroll
            for (int c = 0; c < 8; c++) wdt[c] = 2.0f * (1e-4f + (1.0f - 8e-4f) * ew[c] * inv);

            m = rh[0];
            #pragma unroll
            for (int c = 1; c < 8; c++) m = fmaxf(m, rh[c]);
            sum = 0.0f;
            #pragma unroll
            for (int c = 0; c < 8; c++) { ew[c] = expf(rh[c] - m); sum += ew[c]; }
            inv = 1.0f / sum;
            float hgt[8];
            #pragma unroll
            for (int c = 0; c < 8; c++) hgt[c] = 2.0f * (1e-4f + (1.0f - 8e-4f) * ew[c] * inv);

            float dv[9];
            dv[0] = 1.0f; dv[8] = 1.0f;
            #pragma unroll
            for (int c = 0; c < 7; c++) dv[c + 1] = softplusf(raw[16 + c] + CNST) + 1e-4f;

            const bool mask = (xv <= -0.999f) || (xv >= 0.999f);
            const float xin = mask ? 0.0f : xv;

            float cx = -1.0f, cy = -1.0f;
            float xk = -1.0f, yk = -1.0f, wk = wdt[0], hk = hgt[0], dk = dv[0], dk1 = dv[1];
            #pragma unroll
            for (int i = 0; i < 8; i++) {
                if (cx <= xin) { xk = cx; yk = cy; wk = wdt[i]; hk = hgt[i]; dk = dv[i]; dk1 = dv[i + 1]; }
                cx += wdt[i]; cy += hgt[i];
            }

            const float sk   = hk / wk;
            const float eps  = (xin - xk) / wk;
            const float et   = eps * (1.0f - eps);
            const float e2   = eps * eps;
            const float beta = sk + (dk1 + dk - 2.0f * sk) * et;
            const float alp  = hk * (sk * e2 + dk * et);
            yv[tt] = mask ? xv : (yk + alp / beta);
            const float ome = 1.0f - eps;
            float ld = 2.0f * logf(sk)
                     + logf(dk1 * e2 + 2.0f * sk * et + dk * ome * ome)
                     - 2.0f * logf(beta);
            ldsum += mask ? 0.0f : ld;
        }

        // outputs
        *(float2*)(out + grow + ts) = make_float2(yv[0], yv[1]);
        if (q < 2)
            *(float4*)(out + grow + 8 + q * 4) = *(const float4*)(x + grow + 8 + q * 4);

        ldsum += __shfl_xor_sync(0xffffffffu, ldsum, 1);
        ldsum += __shfl_xor_sync(0xffffffffu, ldsum, 2);
        if (q == 0)
            out[(size_t)B * 16 + row0 + r] = ldsum;
    }
}

extern "C" void kernel_launch(void* const* d_in, const int* in_sizes, int n_in,
                              void* d_out, int out_size) {
    const float* x    = (const float*)d_in[0];
    const float* W0   = (const float*)d_in[1];
    const float* b0   = (const float*)d_in[2];
    const float* W1   = (const float*)d_in[3];
    const float* b1   = (const float*)d_in[4];
    const float* Wout = (const float*)d_in[5];
    const float* bout = (const float*)d_in[6];
    float* out = (float*)d_out;

    const int B = in_sizes[0] / 16;

    prep_w1<<<320, 256>>>(W1);
    prep_wo<<<240, 256>>>(Wout);

    cudaFuncSetAttribute(coupling_hmma_kernel,
                         cudaFuncAttributeMaxDynamicSharedMemorySize, SMEM_BYTES);
    coupling_hmma_kernel<<<B / RB, NT, SMEM_BYTES>>>(x, W0, b0, b1, bout, out, B);
}

// round 6
// speedup vs baseline: 1.5030x; 1.5030x over previous
#include <cuda_runtime.h>
#include <cuda_fp16.h>
#include <math.h>
#include <stdint.h>

#define NT    256
#define RB    128
#define AST   264            // A tile k-stride (fp16): 256 + 8 pad
#define WST   40             // W panel k-stride (fp16): 32 + 8 pad
#define RSTR  193

// ---- smem layout (bytes) ----
#define OFF_A       0                   // 128*264*2 = 67584 fp16
#define OFF_WP      67584               // 2 stages * 20480
#define SLOT_B      20480
#define OFF_W0S     108544              // 8*256 f32 = 8192
#define OFF_B1S     116736              // 256 f32
#define OFF_BOS     117760              // 192 f32
#define OFF_B0S     118528              // 256 f32
#define SMEM_BYTES  119552
// raw buffer (epilogue2): 128*193*4 = 98816 at sm[0], overlaps A+WP (dead then)

#define PAN1_B 20480                    // 256*40*2
#define PAN2_B 15360                    // 192*40*2

// ---- prebuilt fp16 weight panels ----
__device__ __align__(16) __half g_w1[8 * 256 * 40];
__device__ __align__(16) __half g_wo[8 * 192 * 40];

// ---- helpers ----
__device__ __forceinline__ uint32_t smem_u32(const void* p) {
    uint32_t a;
    asm("{ .reg .u64 t; cvta.to.shared.u64 t, %1; cvt.u32.u64 %0, t; }" : "=r"(a) : "l"(p));
    return a;
}
__device__ __forceinline__ void cp16(uint32_t dst, const void* src) {
    asm volatile("cp.async.cg.shared.global [%0], [%1], 16;" :: "r"(dst), "l"(src));
}
#define CP_COMMIT() asm volatile("cp.async.commit_group;")
#define CP_WAIT0()  asm volatile("cp.async.wait_group 0;")

__device__ __forceinline__ void mma16(float* d, uint32_t a0, uint32_t a1, uint32_t a2, uint32_t a3,
                                      uint32_t b0, uint32_t b1) {
    asm volatile("mma.sync.aligned.m16n8k16.row.col.f32.f16.f16.f32 "
                 "{%0,%1,%2,%3}, {%4,%5,%6,%7}, {%8,%9}, {%0,%1,%2,%3};"
                 : "+f"(d[0]), "+f"(d[1]), "+f"(d[2]), "+f"(d[3])
                 : "r"(a0), "r"(a1), "r"(a2), "r"(a3), "r"(b0), "r"(b1));
}

__device__ __forceinline__ float softplusf(float v) {
    return fmaxf(v, 0.0f) + log1pf(expf(-fabsf(v)));
}

// single-product k-panel compute (K=32): d += A * W
template<int NTILES>
__device__ __forceinline__ void panel_compute(const char* A, const char* W,
                                              int akbase, int nbase, int mrow, int qr, int qc,
                                              float d[4][8][4])
{
    #pragma unroll
    for (int ks = 0; ks < 2; ks++) {
        const int kA = akbase + ks * 16 + qc;
        const int kW = ks * 16 + qc;
        uint32_t a[4][4];
        #pragma unroll
        for (int mt = 0; mt < 4; mt++) {
            const uint32_t* ap = (const uint32_t*)(A + ((mrow + mt * 16 + qr) * AST + kA) * 2);
            a[mt][0] = ap[0];
            a[mt][1] = ap[4 * AST];          // +8 rows
            a[mt][2] = ap[4];                // +8 k
            a[mt][3] = ap[4 * AST + 4];
        }
        #pragma unroll
        for (int nt = 0; nt < NTILES; nt++) {
            const uint32_t* bp = (const uint32_t*)(W + ((nbase + nt * 8 + qr) * WST + kW) * 2);
            uint32_t b0 = bp[0], b1 = bp[4];
            #pragma unroll
            for (int mt = 0; mt < 4; mt++)
                mma16(d[mt][nt], a[mt][0], a[mt][1], a[mt][2], a[mt][3], b0, b1);
        }
    }
}

// ---- prep kernels ----
__global__ void prep_w1(const float* __restrict__ W1) {
    int idx = blockIdx.x * blockDim.x + threadIdx.x;      // 81920
    int p = idx / 10240, rem = idx % 10240;
    int n = rem / 40, kk = rem % 40;
    float w = (kk < 32) ? W1[(p * 32 + kk) * 256 + n] : 0.0f;
    g_w1[idx] = __float2half_rn(w);
}
__global__ void prep_wo(const float* __restrict__ Wout) {
    int idx = blockIdx.x * blockDim.x + threadIdx.x;      // 61440
    int p = idx / 7680, rem = idx % 7680;
    int n = rem / 40, kk = rem % 40;
    float w = (kk < 32 && n < 184) ? Wout[(p * 32 + kk) * 184 + n] : 0.0f;
    g_wo[idx] = __float2half_rn(w);
}

// ---- main kernel ----
__global__ void __launch_bounds__(NT, 1)
coupling_hmma_kernel(const float* __restrict__ x,
                     const float* __restrict__ W0,
                     const float* __restrict__ b0,
                     const float* __restrict__ b1,
                     const float* __restrict__ bout,
                     float* __restrict__ out,
                     int B)
{
    extern __shared__ char sm[];
    const int tid = threadIdx.x;
    const int wid = tid >> 5, lane = tid & 31;
    const int mw = wid & 1, nw = wid >> 1;
    const int qr = lane >> 2, qc = (lane & 3) * 2;
    const int row0 = blockIdx.x * RB;
    const uint32_t wp_u32 = smem_u32(sm + OFF_WP);

    float* b0s = (float*)(sm + OFF_B0S);
    float* b1s = (float*)(sm + OFF_B1S);
    float* bos = (float*)(sm + OFF_BOS);
    float* W0s = (float*)(sm + OFF_W0S);

    // ---- prefetch first W1 panel into stage 0 (overlaps GEMM0) ----
    for (int i = tid; i < PAN1_B / 16; i += NT)
        cp16(wp_u32 + i * 16, (const char*)g_w1 + i * 16);
    CP_COMMIT();

    // ---- prologue constants ----
    for (int i = tid; i < 256; i += NT) { b0s[i] = b0[i]; b1s[i] = b1[i]; }
    for (int i = tid; i < 192; i += NT) bos[i] = (i < 184) ? bout[i] : 0.0f;
    for (int i = tid; i < 2048; i += NT) W0s[i] = W0[i];
    __syncthreads();

    // ---- GEMM0 (exact fp32 FFMA): h0 = relu(x2 @ W0 + b0) -> fp16 A tile ----
    {
        const int r = tid & 127, half = tid >> 7;
        const int cb = half * 128;
        const float4* xp = (const float4*)(x + (size_t)(row0 + r) * 16);
        float4 xc = xp[2], xd = xp[3];
        float xv[8] = {xc.x, xc.y, xc.z, xc.w, xd.x, xd.y, xd.z, xd.w};
        for (int c = 0; c < 128; c += 2) {
            float s0 = b0s[cb + c], s1 = b0s[cb + c + 1];
            #pragma unroll
            for (int j = 0; j < 8; j++) {
                s0 = fmaf(xv[j], W0s[j * 256 + cb + c], s0);
                s1 = fmaf(xv[j], W0s[j * 256 + cb + c + 1], s1);
            }
            s0 = fmaxf(s0, 0.0f); s1 = fmaxf(s1, 0.0f);
            *(__half2*)(sm + OFF_A + ((size_t)r * AST + cb + c) * 2) = __floats2half2_rn(s0, s1);
        }
    }
    __syncthreads();

    float d[4][8][4];
    #pragma unroll
    for (int mt = 0; mt < 4; mt++)
        #pragma unroll
        for (int nt = 0; nt < 8; nt++)
            #pragma unroll
            for (int i = 0; i < 4; i++) d[mt][nt][i] = 0.0f;

    // ---- panel pipeline: p 0..7 = GEMM1 (W1), p 8..15 = GEMM2 (Wout) ----
    for (int p = 0; p < 16; p++) {
        CP_WAIT0();
        __syncthreads();

        if (p == 8) {
            // epilogue1: h1 = relu(d + b1) -> fp16 A tile
            #pragma unroll
            for (int mt = 0; mt < 4; mt++) {
                const int r0 = mw * 64 + mt * 16 + qr;
                #pragma unroll
                for (int nt = 0; nt < 8; nt++) {
                    const int c = nw * 64 + nt * 8 + qc;
                    const float g0 = b1s[c], g1 = b1s[c + 1];
                    float v00 = fmaxf(d[mt][nt][0] + g0, 0.f);
                    float v01 = fmaxf(d[mt][nt][1] + g1, 0.f);
                    float v10 = fmaxf(d[mt][nt][2] + g0, 0.f);
                    float v11 = fmaxf(d[mt][nt][3] + g1, 0.f);
                    *(__half2*)(sm + OFF_A + ((size_t)r0 * AST + c) * 2) = __floats2half2_rn(v00, v01);
                    *(__half2*)(sm + OFF_A + ((size_t)(r0 + 8) * AST + c) * 2) = __floats2half2_rn(v10, v11);
                    #pragma unroll
                    for (int i = 0; i < 4; i++) d[mt][nt][i] = 0.0f;
                }
            }
            __syncthreads();
        }

        // issue(p+1) into the other stage (its previous contents consumed last iter)
        if (p + 1 < 16) {
            const int np = p + 1;
            uint32_t dst = wp_u32 + (np & 1) * SLOT_B;
            if (np < 8) {
                const char* src = (const char*)g_w1 + (size_t)np * PAN1_B;
                for (int i = tid; i < PAN1_B / 16; i += NT) cp16(dst + i * 16, src + i * 16);
            } else {
                const char* src = (const char*)g_wo + (size_t)(np - 8) * PAN2_B;
                for (int i = tid; i < PAN2_B / 16; i += NT) cp16(dst + i * 16, src + i * 16);
            }
            CP_COMMIT();
        } else {
            CP_COMMIT();
        }

        const char* wb = sm + OFF_WP + (p & 1) * SLOT_B;
        if (p < 8)
            panel_compute<8>(sm + OFF_A, wb, p * 32, nw * 64, mw * 64, qr, qc, d);
        else
            panel_compute<6>(sm + OFF_A, wb, (p - 8) * 32, nw * 48, mw * 64, qr, qc, d);
    }
    __syncthreads();   // all GEMM2 A/W reads done

    // ---- epilogue2: raw = d + bout -> smem f32 [128][193] (overlaps A+WP) ----
    float* rawS = (float*)sm;
    #pragma unroll
    for (int mt = 0; mt < 4; mt++) {
        const int r0 = mw * 64 + mt * 16 + qr;
        #pragma unroll
        for (int nt = 0; nt < 6; nt++) {
            const int c = nw * 48 + nt * 8 + qc;
            rawS[r0 * RSTR + c]           = d[mt][nt][0] + bos[c];
            rawS[r0 * RSTR + c + 1]       = d[mt][nt][1] + bos[c + 1];
            rawS[(r0 + 8) * RSTR + c]     = d[mt][nt][2] + bos[c];
            rawS[(r0 + 8) * RSTR + c + 1] = d[mt][nt][3] + bos[c + 1];
        }
    }
    __syncthreads();

    // ---- spline: 2 threads/row, 4 transforms each ----
    {
        const int r = tid >> 1;
        const int ts = (tid & 1) * 4;
        const size_t grow = (size_t)(row0 + r) * 16;
        const float4 x1q = *(const float4*)(x + grow + ts);
        const float x1v[4] = {x1q.x, x1q.y, x1q.z, x1q.w};
        const float CNST = logf(expf(1.0f - 1e-4f) - 1.0f);
        float yv[4];
        float ldsum = 0.0f;

        #pragma unroll 1
        for (int tt = 0; tt < 4; tt++) {
            const float* raw = rawS + r * RSTR + (ts + tt) * 23;
            const float xv = x1v[tt];

            float rw[8], rh[8];
            #pragma unroll
            for (int c = 0; c < 8; c++) { rw[c] = raw[c]; rh[c] = raw[8 + c]; }

            float m = rw[0];
            #pragma unroll
            for (int c = 1; c < 8; c++) m = fmaxf(m, rw[c]);
            float sum = 0.0f, ew[8];
            #pragma unroll
            for (int c = 0; c < 8; c++) { ew[c] = expf(rw[c] - m); sum += ew[c]; }
            float inv = 1.0f / sum;
            float wdt[8];
            #pragma unroll
            for (int c = 0; c < 8; c++) wdt[c] = 2.0f * (1e-4f + (1.0f - 8e-4f) * ew[c] * inv);

            m = rh[0];
            #pragma unroll
            for (int c = 1; c < 8; c++) m = fmaxf(m, rh[c]);
            sum = 0.0f;
            #pragma unroll
            for (int c = 0; c < 8; c++) { ew[c] = expf(rh[c] - m); sum += ew[c]; }
            inv = 1.0f / sum;
            float hgt[8];
            #pragma unroll
            for (int c = 0; c < 8; c++) hgt[c] = 2.0f * (1e-4f + (1.0f - 8e-4f) * ew[c] * inv);

            float dv[9];
            dv[0] = 1.0f; dv[8] = 1.0f;
            #pragma unroll
            for (int c = 0; c < 7; c++) dv[c + 1] = softplusf(raw[16 + c] + CNST) + 1e-4f;

            const bool mask = (xv <= -0.999f) || (xv >= 0.999f);
            const float xin = mask ? 0.0f : xv;

            float cx = -1.0f, cy = -1.0f;
            float xk = -1.0f, yk = -1.0f, wk = wdt[0], hk = hgt[0], dk = dv[0], dk1 = dv[1];
            #pragma unroll
            for (int i = 0; i < 8; i++) {
                if (cx <= xin) { xk = cx; yk = cy; wk = wdt[i]; hk = hgt[i]; dk = dv[i]; dk1 = dv[i + 1]; }
                cx += wdt[i]; cy += hgt[i];
            }

            const float sk   = hk / wk;
            const float eps  = (xin - xk) / wk;
            const float et   = eps * (1.0f - eps);
            const float e2   = eps * eps;
            const float beta = sk + (dk1 + dk - 2.0f * sk) * et;
            const float alp  = hk * (sk * e2 + dk * et);
            yv[tt] = mask ? xv : (yk + alp / beta);
            const float ome = 1.0f - eps;
            float ld = 2.0f * logf(sk)
                     + logf(dk1 * e2 + 2.0f * sk * et + dk * ome * ome)
                     - 2.0f * logf(beta);
            ldsum += mask ? 0.0f : ld;
        }

        // outputs
        *(float4*)(out + grow + ts) = make_float4(yv[0], yv[1], yv[2], yv[3]);
        *(float4*)(out + grow + 8 + ts) = *(const float4*)(x + grow + 8 + ts);

        ldsum += __shfl_xor_sync(0xffffffffu, ldsum, 1);
        if ((tid & 1) == 0)
            out[(size_t)B * 16 + row0 + r] = ldsum;
    }
}

extern "C" void kernel_launch(void* const* d_in, const int* in_sizes, int n_in,
                              void* d_out, int out_size) {
    const float* x    = (const float*)d_in[0];
    const float* W0   = (const float*)d_in[1];
    const float* b0   = (const float*)d_in[2];
    const float* W1   = (const float*)d_in[3];
    const float* b1   = (const float*)d_in[4];
    const float* Wout = (const float*)d_in[5];
    const float* bout = (const float*)d_in[6];
    float* out = (float*)d_out;

    const int B = in_sizes[0] / 16;

    prep_w1<<<320, 256>>>(W1);
    prep_wo<<<240, 256>>>(Wout);

    cudaFuncSetAttribute(coupling_hmma_kernel,
                         cudaFuncAttributeMaxDynamicSharedMemorySize, SMEM_BYTES);
    coupling_hmma_kernel<<<B / RB, NT, SMEM_BYTES>>>(x, W0, b0, b1, bout, out, B);
}

// round 7
// speedup vs baseline: 1.6999x; 1.1310x over previous
#include <cuda_runtime.h>
#include <cuda_fp16.h>
#include <math.h>
#include <stdint.h>

#define NT    256
#define RB    128
#define AST   264            // A tile k-stride (fp16): 256 + 8 pad
#define WST   40             // W panel k-stride (fp16): 32 + 8 pad
#define RSTR  193

// ---- smem layout (bytes) ----
#define OFF_A       0                   // 128*264*2 = 67584 fp16
#define OFF_WP      67584               // 3 stages * 20480
#define SLOT_B      20480
#define OFF_A0      108544              // inside WP slot 2: 128*40*2 = 10240
#define OFF_B1S     129024              // 256 f32
#define OFF_BOS     130048              // 192 f32
#define OFF_B0S     130816              // 256 f32
#define OFF_W0P     131840              // 256*40*2 = 20480 (fp16 W0 panel)
#define SMEM_BYTES  152320
// raw buffer (epilogue2): 128*193*4 = 98816 at sm[0], overlaps A+WP (dead then)

#define PAN1_B 20480                    // 256*40*2
#define PAN2_B 15360                    // 192*40*2

// ---- prebuilt fp16 weight panels ----
__device__ __align__(16) __half g_w1[8 * 256 * 40];
__device__ __align__(16) __half g_wo[8 * 192 * 40];
__device__ __align__(16) __half g_w0[256 * 40];     // [W0hi | W0hi | W0lo | 0] k-layout

// ---- helpers ----
__device__ __forceinline__ uint32_t smem_u32(const void* p) {
    uint32_t a;
    asm("{ .reg .u64 t; cvta.to.shared.u64 t, %1; cvt.u32.u64 %0, t; }" : "=r"(a) : "l"(p));
    return a;
}
__device__ __forceinline__ void cp16(uint32_t dst, const void* src) {
    asm volatile("cp.async.cg.shared.global [%0], [%1], 16;" :: "r"(dst), "l"(src));
}
#define CP_COMMIT() asm volatile("cp.async.commit_group;")
#define CP_WAIT0()  asm volatile("cp.async.wait_group 0;")
#define CP_WAIT1()  asm volatile("cp.async.wait_group 1;")

__device__ __forceinline__ void mma16(float* d, uint32_t a0, uint32_t a1, uint32_t a2, uint32_t a3,
                                      uint32_t b0, uint32_t b1) {
    asm volatile("mma.sync.aligned.m16n8k16.row.col.f32.f16.f16.f32 "
                 "{%0,%1,%2,%3}, {%4,%5,%6,%7}, {%8,%9}, {%0,%1,%2,%3};"
                 : "+f"(d[0]), "+f"(d[1]), "+f"(d[2]), "+f"(d[3])
                 : "r"(a0), "r"(a1), "r"(a2), "r"(a3), "r"(b0), "r"(b1));
}

__device__ __forceinline__ float softplusf(float v) {
    return fmaxf(v, 0.0f) + log1pf(expf(-fabsf(v)));
}

// single-product k-panel compute (K=32): d += A * W
template<int NTILES>
__device__ __forceinline__ void panel_compute(const char* A, const char* W,
                                              int akbase, int nbase, int mrow, int qr, int qc,
                                              float d[4][8][4])
{
    #pragma unroll
    for (int ks = 0; ks < 2; ks++) {
        const int kA = akbase + ks * 16 + qc;
        const int kW = ks * 16 + qc;
        uint32_t a[4][4];
        #pragma unroll
        for (int mt = 0; mt < 4; mt++) {
            const uint32_t* ap = (const uint32_t*)(A + ((mrow + mt * 16 + qr) * AST + kA) * 2);
            a[mt][0] = ap[0];
            a[mt][1] = ap[4 * AST];          // +8 rows
            a[mt][2] = ap[4];                // +8 k
            a[mt][3] = ap[4 * AST + 4];
        }
        #pragma unroll
        for (int nt = 0; nt < NTILES; nt++) {
            const uint32_t* bp = (const uint32_t*)(W + ((nbase + nt * 8 + qr) * WST + kW) * 2);
            uint32_t b0 = bp[0], b1 = bp[4];
            #pragma unroll
            for (int mt = 0; mt < 4; mt++)
                mma16(d[mt][nt], a[mt][0], a[mt][1], a[mt][2], a[mt][3], b0, b1);
        }
    }
}

// ---- prep kernels ----
__global__ void prep_w1(const float* __restrict__ W1) {
    int idx = blockIdx.x * blockDim.x + threadIdx.x;      // 81920
    int p = idx / 10240, rem = idx % 10240;
    int n = rem / 40, kk = rem % 40;
    float w = (kk < 32) ? W1[(p * 32 + kk) * 256 + n] : 0.0f;
    g_w1[idx] = __float2half_rn(w);
}
__global__ void prep_wo(const float* __restrict__ Wout) {
    int idx = blockIdx.x * blockDim.x + threadIdx.x;      // 61440
    int p = idx / 7680, rem = idx % 7680;
    int n = rem / 40, kk = rem % 40;
    float w = (kk < 32 && n < 184) ? Wout[(p * 32 + kk) * 184 + n] : 0.0f;
    g_wo[idx] = __float2half_rn(w);
}
__global__ void prep_w0(const float* __restrict__ W0) {
    int idx = blockIdx.x * blockDim.x + threadIdx.x;      // 10240
    int n = idx / 40, kk = idx % 40;
    __half v = __float2half_rn(0.0f);
    if (kk < 16) {                       // W0hi (duplicated for x2hi and x2lo)
        float w = W0[(kk & 7) * 256 + n];
        v = __float2half_rn(w);
    } else if (kk < 24) {                // W0lo
        float w = W0[(kk - 16) * 256 + n];
        __half h = __float2half_rn(w);
        v = __float2half_rn(w - __half2float(h));
    }
    g_w0[idx] = v;
}

// ---- main kernel ----
__global__ void __launch_bounds__(NT, 1)
coupling_hmma_kernel(const float* __restrict__ x,
                     const float* __restrict__ b0,
                     const float* __restrict__ b1,
                     const float* __restrict__ bout,
                     float* __restrict__ out,
                     int B)
{
    extern __shared__ char sm[];
    const int tid = threadIdx.x;
    const int wid = tid >> 5, lane = tid & 31;
    const int mw = wid & 1, nw = wid >> 1;
    const int qr = lane >> 2, qc = (lane & 3) * 2;
    const int row0 = blockIdx.x * RB;
    const uint32_t wp_u32 = smem_u32(sm + OFF_WP);

    float* b0s = (float*)(sm + OFF_B0S);
    float* b1s = (float*)(sm + OFF_B1S);
    float* bos = (float*)(sm + OFF_BOS);

    // ---- prefetch: panel0 (slot0), panel1 (slot1), W0 panel ----
    for (int i = tid; i < PAN1_B / 16; i += NT)
        cp16(wp_u32 + i * 16, (const char*)g_w1 + i * 16);
    CP_COMMIT();
    for (int i = tid; i < PAN1_B / 16; i += NT)
        cp16(wp_u32 + SLOT_B + i * 16, (const char*)g_w1 + PAN1_B + i * 16);
    CP_COMMIT();
    {
        const uint32_t w0p = smem_u32(sm + OFF_W0P);
        for (int i = tid; i < 1280; i += NT)
            cp16(w0p + i * 16, (const char*)g_w0 + i * 16);
    }
    CP_COMMIT();

    // ---- consts + A0 staging (exact hi/lo split of x2) ----
    for (int i = tid; i < 256; i += NT) { b0s[i] = b0[i]; b1s[i] = b1[i]; }
    for (int i = tid; i < 192; i += NT) bos[i] = (i < 184) ? bout[i] : 0.0f;
    if (tid < RB) {
        const float4* xp = (const float4*)(x + (size_t)(row0 + tid) * 16);
        float4 xc = xp[2], xd = xp[3];
        float xv[8] = {xc.x, xc.y, xc.z, xc.w, xd.x, xd.y, xd.z, xd.w};
        __half2* a0 = (__half2*)(sm + OFF_A0 + tid * 40 * 2);
        #pragma unroll
        for (int j = 0; j < 8; j += 2) {
            __half h0 = __float2half_rn(xv[j]);
            __half h1 = __float2half_rn(xv[j + 1]);
            __half l0 = __float2half_rn(xv[j] - __half2float(h0));
            __half l1 = __float2half_rn(xv[j + 1] - __half2float(h1));
            a0[j / 2]      = __half2(h0, h1);   // k 0..7  : x2hi
            a0[4 + j / 2]  = __half2(l0, l1);   // k 8..15 : x2lo
            a0[8 + j / 2]  = __half2(h0, h1);   // k 16..23: x2hi (vs W0lo)
            a0[12 + j / 2] = __half2(__float2half_rn(0.f), __float2half_rn(0.f));
            a0[16 + j / 2] = __half2(__float2half_rn(0.f), __float2half_rn(0.f));
        }
    }
    CP_WAIT0();
    __syncthreads();

    float d[4][8][4];
    #pragma unroll
    for (int mt = 0; mt < 4; mt++)
        #pragma unroll
        for (int nt = 0; nt < 8; nt++)
            #pragma unroll
            for (int i = 0; i < 4; i++) d[mt][nt][i] = 0.0f;

    // ---- GEMM0 on tensor pipe (K=32, exact 3-term hi/lo) ----
    {
        const char* A0 = sm + OFF_A0;
        const char* W0p = sm + OFF_W0P;
        #pragma unroll
        for (int ks = 0; ks < 2; ks++) {
            const int kb = ks * 16 + qc;
            uint32_t a[4][4];
            #pragma unroll
            for (int mt = 0; mt < 4; mt++) {
                const uint32_t* ap = (const uint32_t*)(A0 + ((mw * 64 + mt * 16 + qr) * 40 + kb) * 2);
                a[mt][0] = ap[0];
                a[mt][1] = ap[4 * 40];
                a[mt][2] = ap[4];
                a[mt][3] = ap[4 * 40 + 4];
            }
            #pragma unroll
            for (int nt = 0; nt < 8; nt++) {
                const uint32_t* bp = (const uint32_t*)(W0p + ((nw * 64 + nt * 8 + qr) * 40 + kb) * 2);
                uint32_t bb0 = bp[0], bb1 = bp[4];
                #pragma unroll
                for (int mt = 0; mt < 4; mt++)
                    mma16(d[mt][nt], a[mt][0], a[mt][1], a[mt][2], a[mt][3], bb0, bb1);
            }
        }
    }
    __syncthreads();   // A0 (slot2) reads done before slot2 reused at p=0's issue

    // ---- epilogue0: h0 = relu(d + b0) -> fp16 A tile ----
    #pragma unroll
    for (int mt = 0; mt < 4; mt++) {
        const int r0 = mw * 64 + mt * 16 + qr;
        #pragma unroll
        for (int nt = 0; nt < 8; nt++) {
            const int c = nw * 64 + nt * 8 + qc;
            const float g0 = b0s[c], g1 = b0s[c + 1];
            float v00 = fmaxf(d[mt][nt][0] + g0, 0.f);
            float v01 = fmaxf(d[mt][nt][1] + g1, 0.f);
            float v10 = fmaxf(d[mt][nt][2] + g0, 0.f);
            float v11 = fmaxf(d[mt][nt][3] + g1, 0.f);
            *(__half2*)(sm + OFF_A + ((size_t)r0 * AST + c) * 2) = __floats2half2_rn(v00, v01);
            *(__half2*)(sm + OFF_A + ((size_t)(r0 + 8) * AST + c) * 2) = __floats2half2_rn(v10, v11);
            #pragma unroll
            for (int i = 0; i < 4; i++) d[mt][nt][i] = 0.0f;
        }
    }
    __syncthreads();

    // ---- panel pipeline: p 0..7 = GEMM1 (W1), p 8..15 = GEMM2 (Wout) ----
    // 3 slots, 2 loads in flight. Per iter: wait(panel p) -> sync -> issue(p+2) -> compute(p)
    for (int p = 0; p < 16; p++) {
        CP_WAIT1();
        __syncthreads();

        if (p == 8) {
            // epilogue1: h1 = relu(d + b1) -> fp16 A tile
            #pragma unroll
            for (int mt = 0; mt < 4; mt++) {
                const int r0 = mw * 64 + mt * 16 + qr;
                #pragma unroll
                for (int nt = 0; nt < 8; nt++) {
                    const int c = nw * 64 + nt * 8 + qc;
                    const float g0 = b1s[c], g1 = b1s[c + 1];
                    float v00 = fmaxf(d[mt][nt][0] + g0, 0.f);
                    float v01 = fmaxf(d[mt][nt][1] + g1, 0.f);
                    float v10 = fmaxf(d[mt][nt][2] + g0, 0.f);
                    float v11 = fmaxf(d[mt][nt][3] + g1, 0.f);
                    *(__half2*)(sm + OFF_A + ((size_t)r0 * AST + c) * 2) = __floats2half2_rn(v00, v01);
                    *(__half2*)(sm + OFF_A + ((size_t)(r0 + 8) * AST + c) * 2) = __floats2half2_rn(v10, v11);
                    #pragma unroll
                    for (int i = 0; i < 4; i++) d[mt][nt][i] = 0.0f;
                }
            }
            __syncthreads();
        }

        // issue panel p+2 into slot (p+2)%3 (its previous occupant p-1 done by the sync)
        if (p + 2 < 16) {
            const int np = p + 2;
            uint32_t dst = wp_u32 + (np % 3) * SLOT_B;
            if (np < 8) {
                const char* src = (const char*)g_w1 + (size_t)np * PAN1_B;
                for (int i = tid; i < PAN1_B / 16; i += NT) cp16(dst + i * 16, src + i * 16);
            } else {
                const char* src = (const char*)g_wo + (size_t)(np - 8) * PAN2_B;
                for (int i = tid; i < PAN2_B / 16; i += NT) cp16(dst + i * 16, src + i * 16);
            }
        }
        CP_COMMIT();

        const char* wb = sm + OFF_WP + (p % 3) * SLOT_B;
        if (p < 8)
            panel_compute<8>(sm + OFF_A, wb, p * 32, nw * 64, mw * 64, qr, qc, d);
        else
            panel_compute<6>(sm + OFF_A, wb, (p - 8) * 32, nw * 48, mw * 64, qr, qc, d);
    }
    __syncthreads();   // all GEMM2 A/W reads done

    // ---- epilogue2: raw = d + bout -> smem f32 [128][193] (overlaps A+WP) ----
    float* rawS = (float*)sm;
    #pragma unroll
    for (int mt = 0; mt < 4; mt++) {
        const int r0 = mw * 64 + mt * 16 + qr;
        #pragma unroll
        for (int nt = 0; nt < 6; nt++) {
            const int c = nw * 48 + nt * 8 + qc;
            rawS[r0 * RSTR + c]           = d[mt][nt][0] + bos[c];
            rawS[r0 * RSTR + c + 1]       = d[mt][nt][1] + bos[c + 1];
            rawS[(r0 + 8) * RSTR + c]     = d[mt][nt][2] + bos[c];
            rawS[(r0 + 8) * RSTR + c + 1] = d[mt][nt][3] + bos[c + 1];
        }
    }
    __syncthreads();

    // ---- spline: 2 threads/row, 4 transforms each ----
    {
        const int r = tid >> 1;
        const int ts = (tid & 1) * 4;
        const size_t grow = (size_t)(row0 + r) * 16;
        const float4 x1q = *(const float4*)(x + grow + ts);
        const float x1v[4] = {x1q.x, x1q.y, x1q.z, x1q.w};
        const float CNST = logf(expf(1.0f - 1e-4f) - 1.0f);
        float yv[4];
        float ldsum = 0.0f;

        #pragma unroll 1
        for (int tt = 0; tt < 4; tt++) {
            const float* raw = rawS + r * RSTR + (ts + tt) * 23;
            const float xv = x1v[tt];

            float rw[8], rh[8];
            #pragma unroll
            for (int c = 0; c < 8; c++) { rw[c] = raw[c]; rh[c] = raw[8 + c]; }

            float m = rw[0];
            #pragma unroll
            for (int c = 1; c < 8; c++) m = fmaxf(m, rw[c]);
            float sum = 0.0f, ew[8];
            #pragma unroll
            for (int c = 0; c < 8; c++) { ew[c] = expf(rw[c] - m); sum += ew[c]; }
            float inv = 1.0f / sum;
            float wdt[8];
            #pragma unroll
            for (int c = 0; c < 8; c++) wdt[c] = 2.0f * (1e-4f + (1.0f - 8e-4f) * ew[c] * inv);

            m = rh[0];
            #pragma unroll
            for (int c = 1; c < 8; c++) m = fmaxf(m, rh[c]);
            sum = 0.0f;
            #pragma unroll
            for (int c = 0; c < 8; c++) { ew[c] = expf(rh[c] - m); sum += ew[c]; }
            inv = 1.0f / sum;
            float hgt[8];
            #pragma unroll
            for (int c = 0; c < 8; c++) hgt[c] = 2.0f * (1e-4f + (1.0f - 8e-4f) * ew[c] * inv);

            float dv[9];
            dv[0] = 1.0f; dv[8] = 1.0f;
            #pragma unroll
            for (int c = 0; c < 7; c++) dv[c + 1] = softplusf(raw[16 + c] + CNST) + 1e-4f;

            const bool mask = (xv <= -0.999f) || (xv >= 0.999f);
            const float xin = mask ? 0.0f : xv;

            float cx = -1.0f, cy = -1.0f;
            float xk = -1.0f, yk = -1.0f, wk = wdt[0], hk = hgt[0], dk = dv[0], dk1 = dv[1];
            #pragma unroll
            for (int i = 0; i < 8; i++) {
                if (cx <= xin) { xk = cx; yk = cy; wk = wdt[i]; hk = hgt[i]; dk = dv[i]; dk1 = dv[i + 1]; }
                cx += wdt[i]; cy += hgt[i];
            }

            const float sk   = hk / wk;
            const float eps  = (xin - xk) / wk;
            const float et   = eps * (1.0f - eps);
            const float e2   = eps * eps;
            const float beta = sk + (dk1 + dk - 2.0f * sk) * et;
            const float alp  = hk * (sk * e2 + dk * et);
            yv[tt] = mask ? xv : (yk + alp / beta);
            const float ome = 1.0f - eps;
            float ld = 2.0f * logf(sk)
                     + logf(dk1 * e2 + 2.0f * sk * et + dk * ome * ome)
                     - 2.0f * logf(beta);
            ldsum += mask ? 0.0f : ld;
        }

        // outputs
        *(float4*)(out + grow + ts) = make_float4(yv[0], yv[1], yv[2], yv[3]);
        *(float4*)(out + grow + 8 + ts) = *(const float4*)(x + grow + 8 + ts);

        ldsum += __shfl_xor_sync(0xffffffffu, ldsum, 1);
        if ((tid & 1) == 0)
            out[(size_t)B * 16 + row0 + r] = ldsum;
    }
}

extern "C" void kernel_launch(void* const* d_in, const int* in_sizes, int n_in,
                              void* d_out, int out_size) {
    const float* x    = (const float*)d_in[0];
    const float* W0   = (const float*)d_in[1];
    const float* b0   = (const float*)d_in[2];
    const float* W1   = (const float*)d_in[3];
    const float* b1   = (const float*)d_in[4];
    const float* Wout = (const float*)d_in[5];
    const float* bout = (const float*)d_in[6];
    float* out = (float*)d_out;

    const int B = in_sizes[0] / 16;

    prep_w1<<<320, 256>>>(W1);
    prep_wo<<<240, 256>>>(Wout);
    prep_w0<<<40, 256>>>(W0);

    cudaFuncSetAttribute(coupling_hmma_kernel,
                         cudaFuncAttributeMaxDynamicSharedMemorySize, SMEM_BYTES);
    coupling_hmma_kernel<<<B / RB, NT, SMEM_BYTES>>>(x, b0, b1, bout, out, B);
}

// round 8
// speedup vs baseline: 1.7083x; 1.0050x over previous
#include <cuda_runtime.h>
#include <cuda_fp16.h>
#include <math.h>
#include <stdint.h>

#define NT    256
#define RB    128
#define AST   264            // A tile k-stride (fp16): 256 + 8 pad
#define WST   40             // W panel k-stride (fp16): 32 + 8 pad
#define RSTR  193

// ---- smem layout (bytes) ----
#define OFF_A       0                   // 128*264*2 = 67584 fp16
#define OFF_WP      67584               // 3 stages * 20480
#define SLOT_B      20480
#define OFF_A0      108544              // inside WP slot 2: 128*40*2 = 10240
#define OFF_B1S     129024              // 256 f32
#define OFF_BOS     130048              // 192 f32
#define OFF_B0S     130816              // 256 f32
#define OFF_W0P     131840              // 256*40*2 = 20480 (fp16 W0 panel)
#define SMEM_BYTES  152320
// raw buffer (epilogue2): 128*193*4 = 98816 at sm[0], overlaps A+WP (dead then)

#define PAN1_B 20480                    // 256*40*2
#define PAN2_B 15360                    // 192*40*2

// ---- prebuilt fp16 weight panels ----
__device__ __align__(16) __half g_w1[8 * 256 * 40];
__device__ __align__(16) __half g_wo[8 * 192 * 40];
__device__ __align__(16) __half g_w0[256 * 40];     // [W0hi | W0hi | W0lo | 0] k-layout

// ---- helpers ----
__device__ __forceinline__ uint32_t smem_u32(const void* p) {
    uint32_t a;
    asm("{ .reg .u64 t; cvta.to.shared.u64 t, %1; cvt.u32.u64 %0, t; }" : "=r"(a) : "l"(p));
    return a;
}
__device__ __forceinline__ void cp16(uint32_t dst, const void* src) {
    asm volatile("cp.async.cg.shared.global [%0], [%1], 16;" :: "r"(dst), "l"(src));
}
#define CP_COMMIT() asm volatile("cp.async.commit_group;")
#define CP_WAIT0()  asm volatile("cp.async.wait_group 0;")
#define CP_WAIT1()  asm volatile("cp.async.wait_group 1;")

__device__ __forceinline__ void mma16(float* d, uint32_t a0, uint32_t a1, uint32_t a2, uint32_t a3,
                                      uint32_t b0, uint32_t b1) {
    asm volatile("mma.sync.aligned.m16n8k16.row.col.f32.f16.f16.f32 "
                 "{%0,%1,%2,%3}, {%4,%5,%6,%7}, {%8,%9}, {%0,%1,%2,%3};"
                 : "+f"(d[0]), "+f"(d[1]), "+f"(d[2]), "+f"(d[3])
                 : "r"(a0), "r"(a1), "r"(a2), "r"(a3), "r"(b0), "r"(b1));
}
__device__ __forceinline__ void ldsm4(uint32_t& r0, uint32_t& r1, uint32_t& r2, uint32_t& r3,
                                      uint32_t addr) {
    asm volatile("ldmatrix.sync.aligned.m8n8.x4.shared.b16 {%0,%1,%2,%3}, [%4];"
                 : "=r"(r0), "=r"(r1), "=r"(r2), "=r"(r3) : "r"(addr));
}

__device__ __forceinline__ float softplusf(float v) {
    return fmaxf(v, 0.0f) + log1pf(expf(-fabsf(v)));
}

// k-panel compute (K=32) via ldmatrix.
// aLane: per-lane A addr (row = mrow + (lane&15), k = akbase + (lane>>4)*8)
// wLane: per-lane W addr (n = nbase + (lane&7) + (lane>>4)*8, k = ((lane>>3)&1)*8)
template<int NTILES, int ASTRIDE>
__device__ __forceinline__ void panel_compute(uint32_t aLane, uint32_t wLane, float d[4][8][4])
{
    #pragma unroll
    for (int ks = 0; ks < 2; ks++) {
        const uint32_t aK = aLane + ks * 32;      // +16 halves
        const uint32_t wK = wLane + ks * 32;
        uint32_t a[4][4];
        #pragma unroll
        for (int mt = 0; mt < 4; mt++)
            ldsm4(a[mt][0], a[mt][1], a[mt][2], a[mt][3], aK + mt * (16 * ASTRIDE * 2));
        #pragma unroll
        for (int ntp = 0; ntp < NTILES / 2; ntp++) {
            uint32_t b0, b1, b2, b3;
            ldsm4(b0, b1, b2, b3, wK + ntp * (16 * WST * 2));
            #pragma unroll
            for (int mt = 0; mt < 4; mt++) {
                mma16(d[mt][2 * ntp],     a[mt][0], a[mt][1], a[mt][2], a[mt][3], b0, b1);
                mma16(d[mt][2 * ntp + 1], a[mt][0], a[mt][1], a[mt][2], a[mt][3], b2, b3);
            }
        }
    }
}

// ---- prep kernels ----
__global__ void prep_w1(const float* __restrict__ W1) {
    int idx = blockIdx.x * blockDim.x + threadIdx.x;      // 81920
    int p = idx / 10240, rem = idx % 10240;
    int n = rem / 40, kk = rem % 40;
    float w = (kk < 32) ? W1[(p * 32 + kk) * 256 + n] : 0.0f;
    g_w1[idx] = __float2half_rn(w);
}
__global__ void prep_wo(const float* __restrict__ Wout) {
    int idx = blockIdx.x * blockDim.x + threadIdx.x;      // 61440
    int p = idx / 7680, rem = idx % 7680;
    int n = rem / 40, kk = rem % 40;
    float w = (kk < 32 && n < 184) ? Wout[(p * 32 + kk) * 184 + n] : 0.0f;
    g_wo[idx] = __float2half_rn(w);
}
__global__ void prep_w0(const float* __restrict__ W0) {
    int idx = blockIdx.x * blockDim.x + threadIdx.x;      // 10240
    int n = idx / 40, kk = idx % 40;
    __half v = __float2half_rn(0.0f);
    if (kk < 16) {                       // W0hi (k 0..7 for x2hi, 8..15 for x2lo)
        float w = W0[(kk & 7) * 256 + n];
        v = __float2half_rn(w);
    } else if (kk < 24) {                // W0lo (k 16..23 vs x2hi)
        float w = W0[(kk - 16) * 256 + n];
        __half h = __float2half_rn(w);
        v = __float2half_rn(w - __half2float(h));
    }
    g_w0[idx] = v;
}

// ---- main kernel ----
__global__ void __launch_bounds__(NT, 1)
coupling_hmma_kernel(const float* __restrict__ x,
                     const float* __restrict__ b0,
                     const float* __restrict__ b1,
                     const float* __restrict__ bout,
                     float* __restrict__ out,
                     int B)
{
    extern __shared__ char sm[];
    const int tid = threadIdx.x;
    const int wid = tid >> 5, lane = tid & 31;
    const int mw = wid & 1, nw = wid >> 1;
    const int qr = lane >> 2, qc = (lane & 3) * 2;
    const int row0 = blockIdx.x * RB;
    const uint32_t sm_u32 = smem_u32(sm);
    const uint32_t wp_u32 = sm_u32 + OFF_WP;

    float* b0s = (float*)(sm + OFF_B0S);
    float* b1s = (float*)(sm + OFF_B1S);
    float* bos = (float*)(sm + OFF_BOS);

    // per-lane ldmatrix address components
    const int aRow = (lane & 15);
    const int aKof = (lane >> 4) * 8;
    const int wRow = (lane & 7) + ((lane >> 4) * 8);
    const int wKof = ((lane >> 3) & 1) * 8;
    // A-tile lane base (row = mw*64 + aRow), k starts at aKof
    const uint32_t aLaneA = sm_u32 + OFF_A + (((mw * 64 + aRow) * AST) + aKof) * 2;
    // W panel lane offsets (relative to slot base)
    const uint32_t wRel1 = (((nw * 64 + wRow) * WST) + wKof) * 2;   // GEMM1: nbase = nw*64
    const uint32_t wRel2 = (((nw * 48 + wRow) * WST) + wKof) * 2;   // GEMM2: nbase = nw*48

    // ---- prefetch: panel0 (slot0), panel1 (slot1), W0 panel ----
    for (int i = tid; i < PAN1_B / 16; i += NT)
        cp16(wp_u32 + i * 16, (const char*)g_w1 + i * 16);
    CP_COMMIT();
    for (int i = tid; i < PAN1_B / 16; i += NT)
        cp16(wp_u32 + SLOT_B + i * 16, (const char*)g_w1 + PAN1_B + i * 16);
    CP_COMMIT();
    {
        const uint32_t w0p = sm_u32 + OFF_W0P;
        for (int i = tid; i < 1280; i += NT)
            cp16(w0p + i * 16, (const char*)g_w0 + i * 16);
    }
    CP_COMMIT();

    // ---- consts + A0 staging (exact hi/lo split of x2) ----
    for (int i = tid; i < 256; i += NT) { b0s[i] = b0[i]; b1s[i] = b1[i]; }
    for (int i = tid; i < 192; i += NT) bos[i] = (i < 184) ? bout[i] : 0.0f;
    if (tid < RB) {
        const float4* xp = (const float4*)(x + (size_t)(row0 + tid) * 16);
        float4 xc = xp[2], xd = xp[3];
        float xv[8] = {xc.x, xc.y, xc.z, xc.w, xd.x, xd.y, xd.z, xd.w};
        __half2* a0 = (__half2*)(sm + OFF_A0 + tid * 40 * 2);
        #pragma unroll
        for (int j = 0; j < 8; j += 2) {
            __half h0 = __float2half_rn(xv[j]);
            __half h1 = __float2half_rn(xv[j + 1]);
            __half l0 = __float2half_rn(xv[j] - __half2float(h0));
            __half l1 = __float2half_rn(xv[j + 1] - __half2float(h1));
            a0[j / 2]      = __half2(h0, h1);   // k 0..7  : x2hi
            a0[4 + j / 2]  = __half2(l0, l1);   // k 8..15 : x2lo
            a0[8 + j / 2]  = __half2(h0, h1);   // k 16..23: x2hi (vs W0lo)
            a0[12 + j / 2] = __half2(__float2half_rn(0.f), __float2half_rn(0.f));
            a0[16 + j / 2] = __half2(__float2half_rn(0.f), __float2half_rn(0.f));
        }
    }
    CP_WAIT0();
    __syncthreads();

    float d[4][8][4];
    #pragma unroll
    for (int mt = 0; mt < 4; mt++)
        #pragma unroll
        for (int nt = 0; nt < 8; nt++)
            #pragma unroll
            for (int i = 0; i < 4; i++) d[mt][nt][i] = 0.0f;

    // ---- GEMM0 on tensor pipe (K=32, exact 3-term hi/lo) ----
    {
        const uint32_t aLane0 = sm_u32 + OFF_A0 + (((mw * 64 + aRow) * 40) + aKof) * 2;
        const uint32_t wLane0 = sm_u32 + OFF_W0P + wRel1;
        panel_compute<8, 40>(aLane0, wLane0, d);
    }
    __syncthreads();   // A0 (slot2) reads done before slot2 reused at p=0's issue

    // ---- epilogue0: h0 = relu(d + b0) -> fp16 A tile ----
    #pragma unroll
    for (int mt = 0; mt < 4; mt++) {
        const int r0 = mw * 64 + mt * 16 + qr;
        #pragma unroll
        for (int nt = 0; nt < 8; nt++) {
            const int c = nw * 64 + nt * 8 + qc;
            const float g0 = b0s[c], g1 = b0s[c + 1];
            float v00 = fmaxf(d[mt][nt][0] + g0, 0.f);
            float v01 = fmaxf(d[mt][nt][1] + g1, 0.f);
            float v10 = fmaxf(d[mt][nt][2] + g0, 0.f);
            float v11 = fmaxf(d[mt][nt][3] + g1, 0.f);
            *(__half2*)(sm + OFF_A + ((size_t)r0 * AST + c) * 2) = __floats2half2_rn(v00, v01);
            *(__half2*)(sm + OFF_A + ((size_t)(r0 + 8) * AST + c) * 2) = __floats2half2_rn(v10, v11);
            #pragma unroll
            for (int i = 0; i < 4; i++) d[mt][nt][i] = 0.0f;
        }
    }
    __syncthreads();

    // ---- panel pipeline: p 0..7 = GEMM1 (W1), p 8..15 = GEMM2 (Wout) ----
    // 3 slots, 2 loads in flight. Per iter: wait(panel p) -> sync -> issue(p+2) -> compute(p)
    for (int p = 0; p < 16; p++) {
        CP_WAIT1();
        __syncthreads();

        if (p == 8) {
            // epilogue1: h1 = relu(d + b1) -> fp16 A tile
            #pragma unroll
            for (int mt = 0; mt < 4; mt++) {
                const int r0 = mw * 64 + mt * 16 + qr;
                #pragma unroll
                for (int nt = 0; nt < 8; nt++) {
                    const int c = nw * 64 + nt * 8 + qc;
                    const float g0 = b1s[c], g1 = b1s[c + 1];
                    float v00 = fmaxf(d[mt][nt][0] + g0, 0.f);
                    float v01 = fmaxf(d[mt][nt][1] + g1, 0.f);
                    float v10 = fmaxf(d[mt][nt][2] + g0, 0.f);
                    float v11 = fmaxf(d[mt][nt][3] + g1, 0.f);
                    *(__half2*)(sm + OFF_A + ((size_t)r0 * AST + c) * 2) = __floats2half2_rn(v00, v01);
                    *(__half2*)(sm + OFF_A + ((size_t)(r0 + 8) * AST + c) * 2) = __floats2half2_rn(v10, v11);
                    #pragma unroll
                    for (int i = 0; i < 4; i++) d[mt][nt][i] = 0.0f;
                }
            }
            __syncthreads();
        }

        // issue panel p+2 into slot (p+2)%3 (its previous occupant p-1 done by the sync)
        if (p + 2 < 16) {
            const int np = p + 2;
            uint32_t dst = wp_u32 + (np % 3) * SLOT_B;
            if (np < 8) {
                const char* src = (const char*)g_w1 + (size_t)np * PAN1_B;
                for (int i = tid; i < PAN1_B / 16; i += NT) cp16(dst + i * 16, src + i * 16);
            } else {
                const char* src = (const char*)g_wo + (size_t)(np - 8) * PAN2_B;
                for (int i = tid; i < PAN2_B / 16; i += NT) cp16(dst + i * 16, src + i * 16);
            }
        }
        CP_COMMIT();

        const uint32_t slot = wp_u32 + (p % 3) * SLOT_B;
        if (p < 8)
            panel_compute<8, AST>(aLaneA + p * 64, slot + wRel1, d);          // akbase = p*32 halves
        else
            panel_compute<6, AST>(aLaneA + (p - 8) * 64, slot + wRel2, d);
    }
    __syncthreads();   // all GEMM2 A/W reads done

    // ---- epilogue2: raw = d + bout -> smem f32 [128][193] (overlaps A+WP) ----
    float* rawS = (float*)sm;
    #pragma unroll
    for (int mt = 0; mt < 4; mt++) {
        const int r0 = mw * 64 + mt * 16 + qr;
        #pragma unroll
        for (int nt = 0; nt < 6; nt++) {
            const int c = nw * 48 + nt * 8 + qc;
            rawS[r0 * RSTR + c]           = d[mt][nt][0] + bos[c];
            rawS[r0 * RSTR + c + 1]       = d[mt][nt][1] + bos[c + 1];
            rawS[(r0 + 8) * RSTR + c]     = d[mt][nt][2] + bos[c];
            rawS[(r0 + 8) * RSTR + c + 1] = d[mt][nt][3] + bos[c + 1];
        }
    }
    __syncthreads();

    // ---- spline: 2 threads/row, 4 transforms each ----
    {
        const int r = tid >> 1;
        const int ts = (tid & 1) * 4;
        const size_t grow = (size_t)(row0 + r) * 16;
        const float4 x1q = *(const float4*)(x + grow + ts);
        const float x1v[4] = {x1q.x, x1q.y, x1q.z, x1q.w};
        const float CNST = logf(expf(1.0f - 1e-4f) - 1.0f);
        float yv[4];
        float ldsum = 0.0f;

        #pragma unroll 1
        for (int tt = 0; tt < 4; tt++) {
            const float* raw = rawS + r * RSTR + (ts + tt) * 23;
            const float xv = x1v[tt];

            float rw[8], rh[8];
            #pragma unroll
            for (int c = 0; c < 8; c++) { rw[c] = raw[c]; rh[c] = raw[8 + c]; }

            float m = rw[0];
            #pragma unroll
            for (int c = 1; c < 8; c++) m = fmaxf(m, rw[c]);
            float sum = 0.0f, ew[8];
            #pragma unroll
            for (int c = 0; c < 8; c++) { ew[c] = expf(rw[c] - m); sum += ew[c]; }
            float inv = 1.0f / sum;
            float wdt[8];
            #pragma unroll
            for (int c = 0; c < 8; c++) wdt[c] = 2.0f * (1e-4f + (1.0f - 8e-4f) * ew[c] * inv);

            m = rh[0];
            #pragma unroll
            for (int c = 1; c < 8; c++) m = fmaxf(m, rh[c]);
            sum = 0.0f;
            #pragma unroll
            for (int c = 0; c < 8; c++) { ew[c] = expf(rh[c] - m); sum += ew[c]; }
            inv = 1.0f / sum;
            float hgt[8];
            #pragma unroll
            for (int c = 0; c < 8; c++) hgt[c] = 2.0f * (1e-4f + (1.0f - 8e-4f) * ew[c] * inv);

            float dv[9];
            dv[0] = 1.0f; dv[8] = 1.0f;
            #pragma unroll
            for (int c = 0; c < 7; c++) dv[c + 1] = softplusf(raw[16 + c] + CNST) + 1e-4f;

            const bool mask = (xv <= -0.999f) || (xv >= 0.999f);
            const float xin = mask ? 0.0f : xv;

            float cx = -1.0f, cy = -1.0f;
            float xk = -1.0f, yk = -1.0f, wk = wdt[0], hk = hgt[0], dk = dv[0], dk1 = dv[1];
            #pragma unroll
            for (int i = 0; i < 8; i++) {
                if (cx <= xin) { xk = cx; yk = cy; wk = wdt[i]; hk = hgt[i]; dk = dv[i]; dk1 = dv[i + 1]; }
                cx += wdt[i]; cy += hgt[i];
            }

            const float sk   = hk / wk;
            const float eps  = (xin - xk) / wk;
            const float et   = eps * (1.0f - eps);
            const float e2   = eps * eps;
            const float beta = sk + (dk1 + dk - 2.0f * sk) * et;
            const float alp  = hk * (sk * e2 + dk * et);
            yv[tt] = mask ? xv : (yk + alp / beta);
            const float ome = 1.0f - eps;
            float ld = 2.0f * logf(sk)
                     + logf(dk1 * e2 + 2.0f * sk * et + dk * ome * ome)
                     - 2.0f * logf(beta);
            ldsum += mask ? 0.0f : ld;
        }

        // outputs
        *(float4*)(out + grow + ts) = make_float4(yv[0], yv[1], yv[2], yv[3]);
        *(float4*)(out + grow + 8 + ts) = *(const float4*)(x + grow + 8 + ts);

        ldsum += __shfl_xor_sync(0xffffffffu, ldsum, 1);
        if ((tid & 1) == 0)
            out[(size_t)B * 16 + row0 + r] = ldsum;
    }
}

extern "C" void kernel_launch(void* const* d_in, const int* in_sizes, int n_in,
                              void* d_out, int out_size) {
    const float* x    = (const float*)d_in[0];
    const float* W0   = (const float*)d_in[1];
    const float* b0   = (const float*)d_in[2];
    const float* W1   = (const float*)d_in[3];
    const float* b1   = (const float*)d_in[4];
    const float* Wout = (const float*)d_in[5];
    const float* bout = (const float*)d_in[6];
    float* out = (float*)d_out;

    const int B = in_sizes[0] / 16;

    prep_w1<<<320, 256>>>(W1);
    prep_wo<<<240, 256>>>(Wout);
    prep_w0<<<40, 256>>>(W0);

    cudaFuncSetAttribute(coupling_hmma_kernel,
                         cudaFuncAttributeMaxDynamicSharedMemorySize, SMEM_BYTES);
    coupling_hmma_kernel<<<B / RB, NT, SMEM_BYTES>>>(x, b0, b1, bout, out, B);
}

// round 9
// speedup vs baseline: 1.7609x; 1.0307x over previous
#include <cuda_runtime.h>
#include <cuda_fp16.h>
#include <math.h>
#include <stdint.h>

#define NT    512
#define RB    128
#define AST   264            // A tile k-stride (fp16): 256 + 8 pad
#define WST   40             // W panel k-stride (fp16): 32 + 8 pad
#define RSTR  193

// ---- smem layout (bytes) ----
#define OFF_A       0                   // 128*264*2 = 67584 fp16
#define OFF_WP      67584               // 3 stages * 20480
#define SLOT_B      20480
#define OFF_A0      108544              // inside WP slot 2: 128*40*2 = 10240
#define OFF_B1S     129024              // 256 f32
#define OFF_BOS     130048              // 192 f32
#define OFF_B0S     130816              // 256 f32
#define OFF_W0P     131840              // 256*40*2 = 20480 (fp16 W0 panel)
#define SMEM_BYTES  152320
// raw buffer (epilogue2): 128*193*4 = 98816 at sm[0], overlaps A+WP (dead then)

#define PAN1_B 20480                    // 256*40*2
#define PAN2_B 15360                    // 192*40*2

// ---- prebuilt fp16 weight panels ----
__device__ __align__(16) __half g_w1[8 * 256 * 40];
__device__ __align__(16) __half g_wo[8 * 192 * 40];
__device__ __align__(16) __half g_w0[256 * 40];     // [W0hi | W0hi | W0lo | 0] k-layout

// ---- helpers ----
__device__ __forceinline__ uint32_t smem_u32(const void* p) {
    uint32_t a;
    asm("{ .reg .u64 t; cvta.to.shared.u64 t, %1; cvt.u32.u64 %0, t; }" : "=r"(a) : "l"(p));
    return a;
}
__device__ __forceinline__ void cp16(uint32_t dst, const void* src) {
    asm volatile("cp.async.cg.shared.global [%0], [%1], 16;" :: "r"(dst), "l"(src));
}
#define CP_COMMIT() asm volatile("cp.async.commit_group;")
#define CP_WAIT0()  asm volatile("cp.async.wait_group 0;")
#define CP_WAIT1()  asm volatile("cp.async.wait_group 1;")

__device__ __forceinline__ void mma16(float* d, uint32_t a0, uint32_t a1, uint32_t a2, uint32_t a3,
                                      uint32_t b0, uint32_t b1) {
    asm volatile("mma.sync.aligned.m16n8k16.row.col.f32.f16.f16.f32 "
                 "{%0,%1,%2,%3}, {%4,%5,%6,%7}, {%8,%9}, {%0,%1,%2,%3};"
                 : "+f"(d[0]), "+f"(d[1]), "+f"(d[2]), "+f"(d[3])
                 : "r"(a0), "r"(a1), "r"(a2), "r"(a3), "r"(b0), "r"(b1));
}
__device__ __forceinline__ void ldsm4(uint32_t& r0, uint32_t& r1, uint32_t& r2, uint32_t& r3,
                                      uint32_t addr) {
    asm volatile("ldmatrix.sync.aligned.m8n8.x4.shared.b16 {%0,%1,%2,%3}, [%4];"
                 : "=r"(r0), "=r"(r1), "=r"(r2), "=r"(r3) : "r"(addr));
}

__device__ __forceinline__ float softplusf(float v) {
    return fmaxf(v, 0.0f) + log1pf(expf(-fabsf(v)));
}

// k-panel compute (K=32) via ldmatrix; 2 m-tiles (32-row warp tile)
template<int NTILES, int ASTRIDE>
__device__ __forceinline__ void panel_compute(uint32_t aLane, uint32_t wLane, float d[2][8][4])
{
    #pragma unroll
    for (int ks = 0; ks < 2; ks++) {
        const uint32_t aK = aLane + ks * 32;      // +16 halves
        const uint32_t wK = wLane + ks * 32;
        uint32_t a[2][4];
        #pragma unroll
        for (int mt = 0; mt < 2; mt++)
            ldsm4(a[mt][0], a[mt][1], a[mt][2], a[mt][3], aK + mt * (16 * ASTRIDE * 2));
        #pragma unroll
        for (int ntp = 0; ntp < NTILES / 2; ntp++) {
            uint32_t b0, b1, b2, b3;
            ldsm4(b0, b1, b2, b3, wK + ntp * (16 * WST * 2));
            #pragma unroll
            for (int mt = 0; mt < 2; mt++) {
                mma16(d[mt][2 * ntp],     a[mt][0], a[mt][1], a[mt][2], a[mt][3], b0, b1);
                mma16(d[mt][2 * ntp + 1], a[mt][0], a[mt][1], a[mt][2], a[mt][3], b2, b3);
            }
        }
    }
}

// ---- prep kernels ----
__global__ void prep_w1(const float* __restrict__ W1) {
    int idx = blockIdx.x * blockDim.x + threadIdx.x;      // 81920
    int p = idx / 10240, rem = idx % 10240;
    int n = rem / 40, kk = rem % 40;
    float w = (kk < 32) ? W1[(p * 32 + kk) * 256 + n] : 0.0f;
    g_w1[idx] = __float2half_rn(w);
}
__global__ void prep_wo(const float* __restrict__ Wout) {
    int idx = blockIdx.x * blockDim.x + threadIdx.x;      // 61440
    int p = idx / 7680, rem = idx % 7680;
    int n = rem / 40, kk = rem % 40;
    float w = (kk < 32 && n < 184) ? Wout[(p * 32 + kk) * 184 + n] : 0.0f;
    g_wo[idx] = __float2half_rn(w);
}
__global__ void prep_w0(const float* __restrict__ W0) {
    int idx = blockIdx.x * blockDim.x + threadIdx.x;      // 10240
    int n = idx / 40, kk = idx % 40;
    __half v = __float2half_rn(0.0f);
    if (kk < 16) {                       // W0hi (k 0..7 for x2hi, 8..15 for x2lo)
        float w = W0[(kk & 7) * 256 + n];
        v = __float2half_rn(w);
    } else if (kk < 24) {                // W0lo (k 16..23 vs x2hi)
        float w = W0[(kk - 16) * 256 + n];
        __half h = __float2half_rn(w);
        v = __float2half_rn(w - __half2float(h));
    }
    g_w0[idx] = v;
}

// ---- main kernel ----
__global__ void __launch_bounds__(NT, 1)
coupling_hmma_kernel(const float* __restrict__ x,
                     const float* __restrict__ b0,
                     const float* __restrict__ b1,
                     const float* __restrict__ bout,
                     float* __restrict__ out,
                     int B)
{
    extern __shared__ char sm[];
    const int tid = threadIdx.x;
    const int wid = tid >> 5, lane = tid & 31;
    const int mw = wid & 3, nw = wid >> 2;          // 4 m-warps x 4 n-warps
    const int qr = lane >> 2, qc = (lane & 3) * 2;
    const int row0 = blockIdx.x * RB;
    const uint32_t sm_u32 = smem_u32(sm);
    const uint32_t wp_u32 = sm_u32 + OFF_WP;

    float* b0s = (float*)(sm + OFF_B0S);
    float* b1s = (float*)(sm + OFF_B1S);
    float* bos = (float*)(sm + OFF_BOS);

    // per-lane ldmatrix address components
    const int aRow = (lane & 15);
    const int aKof = (lane >> 4) * 8;
    const int wRow = (lane & 7) + ((lane >> 4) * 8);
    const int wKof = ((lane >> 3) & 1) * 8;
    const uint32_t aLaneA = sm_u32 + OFF_A + (((mw * 32 + aRow) * AST) + aKof) * 2;
    const uint32_t wRel1 = (((nw * 64 + wRow) * WST) + wKof) * 2;   // GEMM1: nbase = nw*64
    const uint32_t wRel2 = (((nw * 48 + wRow) * WST) + wKof) * 2;   // GEMM2: nbase = nw*48

    // ---- prefetch: panel0 (slot0), panel1 (slot1), W0 panel ----
    for (int i = tid; i < PAN1_B / 16; i += NT)
        cp16(wp_u32 + i * 16, (const char*)g_w1 + i * 16);
    CP_COMMIT();
    for (int i = tid; i < PAN1_B / 16; i += NT)
        cp16(wp_u32 + SLOT_B + i * 16, (const char*)g_w1 + PAN1_B + i * 16);
    CP_COMMIT();
    {
        const uint32_t w0p = sm_u32 + OFF_W0P;
        for (int i = tid; i < 1280; i += NT)
            cp16(w0p + i * 16, (const char*)g_w0 + i * 16);
    }
    CP_COMMIT();

    // ---- consts + A0 staging (exact hi/lo split of x2) ----
    for (int i = tid; i < 256; i += NT) { b0s[i] = b0[i]; b1s[i] = b1[i]; }
    for (int i = tid; i < 192; i += NT) bos[i] = (i < 184) ? bout[i] : 0.0f;
    if (tid < RB) {
        const float4* xp = (const float4*)(x + (size_t)(row0 + tid) * 16);
        float4 xc = xp[2], xd = xp[3];
        float xv[8] = {xc.x, xc.y, xc.z, xc.w, xd.x, xd.y, xd.z, xd.w};
        __half2* a0 = (__half2*)(sm + OFF_A0 + tid * 40 * 2);
        #pragma unroll
        for (int j = 0; j < 8; j += 2) {
            __half h0 = __float2half_rn(xv[j]);
            __half h1 = __float2half_rn(xv[j + 1]);
            __half l0 = __float2half_rn(xv[j] - __half2float(h0));
            __half l1 = __float2half_rn(xv[j + 1] - __half2float(h1));
            a0[j / 2]      = __half2(h0, h1);   // k 0..7  : x2hi
            a0[4 + j / 2]  = __half2(l0, l1);   // k 8..15 : x2lo
            a0[8 + j / 2]  = __half2(h0, h1);   // k 16..23: x2hi (vs W0lo)
            a0[12 + j / 2] = __half2(__float2half_rn(0.f), __float2half_rn(0.f));
            a0[16 + j / 2] = __half2(__float2half_rn(0.f), __float2half_rn(0.f));
        }
    }
    CP_WAIT0();
    __syncthreads();

    float d[2][8][4];
    #pragma unroll
    for (int mt = 0; mt < 2; mt++)
        #pragma unroll
        for (int nt = 0; nt < 8; nt++)
            #pragma unroll
            for (int i = 0; i < 4; i++) d[mt][nt][i] = 0.0f;

    // ---- GEMM0 on tensor pipe (K=32, exact 3-term hi/lo) ----
    {
        const uint32_t aLane0 = sm_u32 + OFF_A0 + (((mw * 32 + aRow) * 40) + aKof) * 2;
        const uint32_t wLane0 = sm_u32 + OFF_W0P + wRel1;
        panel_compute<8, 40>(aLane0, wLane0, d);
    }
    __syncthreads();   // A0 (slot2) reads done before slot2 reused at p=0's issue

    // ---- epilogue0: h0 = relu(d + b0) -> fp16 A tile ----
    #pragma unroll
    for (int mt = 0; mt < 2; mt++) {
        const int r0 = mw * 32 + mt * 16 + qr;
        #pragma unroll
        for (int nt = 0; nt < 8; nt++) {
            const int c = nw * 64 + nt * 8 + qc;
            const float g0 = b0s[c], g1 = b0s[c + 1];
            float v00 = fmaxf(d[mt][nt][0] + g0, 0.f);
            float v01 = fmaxf(d[mt][nt][1] + g1, 0.f);
            float v10 = fmaxf(d[mt][nt][2] + g0, 0.f);
            float v11 = fmaxf(d[mt][nt][3] + g1, 0.f);
            *(__half2*)(sm + OFF_A + ((size_t)r0 * AST + c) * 2) = __floats2half2_rn(v00, v01);
            *(__half2*)(sm + OFF_A + ((size_t)(r0 + 8) * AST + c) * 2) = __floats2half2_rn(v10, v11);
            #pragma unroll
            for (int i = 0; i < 4; i++) d[mt][nt][i] = 0.0f;
        }
    }
    __syncthreads();

    // ---- panel pipeline: p 0..7 = GEMM1 (W1), p 8..15 = GEMM2 (Wout) ----
    for (int p = 0; p < 16; p++) {
        CP_WAIT1();
        __syncthreads();

        if (p == 8) {
            // epilogue1: h1 = relu(d + b1) -> fp16 A tile
            #pragma unroll
            for (int mt = 0; mt < 2; mt++) {
                const int r0 = mw * 32 + mt * 16 + qr;
                #pragma unroll
                for (int nt = 0; nt < 8; nt++) {
                    const int c = nw * 64 + nt * 8 + qc;
                    const float g0 = b1s[c], g1 = b1s[c + 1];
                    float v00 = fmaxf(d[mt][nt][0] + g0, 0.f);
                    float v01 = fmaxf(d[mt][nt][1] + g1, 0.f);
                    float v10 = fmaxf(d[mt][nt][2] + g0, 0.f);
                    float v11 = fmaxf(d[mt][nt][3] + g1, 0.f);
                    *(__half2*)(sm + OFF_A + ((size_t)r0 * AST + c) * 2) = __floats2half2_rn(v00, v01);
                    *(__half2*)(sm + OFF_A + ((size_t)(r0 + 8) * AST + c) * 2) = __floats2half2_rn(v10, v11);
                    #pragma unroll
                    for (int i = 0; i < 4; i++) d[mt][nt][i] = 0.0f;
                }
            }
            __syncthreads();
        }

        // issue panel p+2 into slot (p+2)%3
        if (p + 2 < 16) {
            const int np = p + 2;
            uint32_t dst = wp_u32 + (np % 3) * SLOT_B;
            if (np < 8) {
                const char* src = (const char*)g_w1 + (size_t)np * PAN1_B;
                for (int i = tid; i < PAN1_B / 16; i += NT) cp16(dst + i * 16, src + i * 16);
            } else {
                const char* src = (const char*)g_wo + (size_t)(np - 8) * PAN2_B;
                for (int i = tid; i < PAN2_B / 16; i += NT) cp16(dst + i * 16, src + i * 16);
            }
        }
        CP_COMMIT();

        const uint32_t slot = wp_u32 + (p % 3) * SLOT_B;
        if (p < 8)
            panel_compute<8, AST>(aLaneA + p * 64, slot + wRel1, d);          // akbase = p*32 halves
        else
            panel_compute<6, AST>(aLaneA + (p - 8) * 64, slot + wRel2, d);
    }
    __syncthreads();   // all GEMM2 A/W reads done

    // ---- epilogue2: raw = d + bout -> smem f32 [128][193] (overlaps A+WP) ----
    float* rawS = (float*)sm;
    #pragma unroll
    for (int mt = 0; mt < 2; mt++) {
        const int r0 = mw * 32 + mt * 16 + qr;
        #pragma unroll
        for (int nt = 0; nt < 6; nt++) {
            const int c = nw * 48 + nt * 8 + qc;
            rawS[r0 * RSTR + c]           = d[mt][nt][0] + bos[c];
            rawS[r0 * RSTR + c + 1]       = d[mt][nt][1] + bos[c + 1];
            rawS[(r0 + 8) * RSTR + c]     = d[mt][nt][2] + bos[c];
            rawS[(r0 + 8) * RSTR + c + 1] = d[mt][nt][3] + bos[c + 1];
        }
    }
    __syncthreads();

    // ---- spline: 4 threads/row, 2 transforms each ----
    {
        const int r = tid >> 2;
        const int q = tid & 3;
        const int ts = q * 2;
        const size_t grow = (size_t)(row0 + r) * 16;
        const float2 x1p = *(const float2*)(x + grow + ts);
        const float x1v[2] = {x1p.x, x1p.y};
        const float CNST = logf(expf(1.0f - 1e-4f) - 1.0f);
        float yv[2];
        float ldsum = 0.0f;

        #pragma unroll 1
        for (int tt = 0; tt < 2; tt++) {
            const float* raw = rawS + r * RSTR + (ts + tt) * 23;
            const float xv = x1v[tt];

            float rw[8], rh[8];
            #pragma unroll
            for (int c = 0; c < 8; c++) { rw[c] = raw[c]; rh[c] = raw[8 + c]; }

            float m = rw[0];
            #pragma unroll
            for (int c = 1; c < 8; c++) m = fmaxf(m, rw[c]);
            float sum = 0.0f, ew[8];
            #pragma unroll
            for (int c = 0; c < 8; c++) { ew[c] = expf(rw[c] - m); sum += ew[c]; }
            float inv = 1.0f / sum;
            float wdt[8];
            #pragma unroll
            for (int c = 0; c < 8; c++) wdt[c] = 2.0f * (1e-4f + (1.0f - 8e-4f) * ew[c] * inv);

            m = rh[0];
            #pragma unroll
            for (int c = 1; c < 8; c++) m = fmaxf(m, rh[c]);
            sum = 0.0f;
            #pragma unroll
            for (int c = 0; c < 8; c++) { ew[c] = expf(rh[c] - m); sum += ew[c]; }
            inv = 1.0f / sum;
            float hgt[8];
            #pragma unroll
            for (int c = 0; c < 8; c++) hgt[c] = 2.0f * (1e-4f + (1.0f - 8e-4f) * ew[c] * inv);

            float dv[9];
            dv[0] = 1.0f; dv[8] = 1.0f;
            #pragma unroll
            for (int c = 0; c < 7; c++) dv[c + 1] = softplusf(raw[16 + c] + CNST) + 1e-4f;

            const bool mask = (xv <= -0.999f) || (xv >= 0.999f);
            const float xin = mask ? 0.0f : xv;

            float cx = -1.0f, cy = -1.0f;
            float xk = -1.0f, yk = -1.0f, wk = wdt[0], hk = hgt[0], dk = dv[0], dk1 = dv[1];
            #pragma unroll
            for (int i = 0; i < 8; i++) {
                if (cx <= xin) { xk = cx; yk = cy; wk = wdt[i]; hk = hgt[i]; dk = dv[i]; dk1 = dv[i + 1]; }
                cx += wdt[i]; cy += hgt[i];
            }

            const float sk   = hk / wk;
            const float eps  = (xin - xk) / wk;
            const float et   = eps * (1.0f - eps);
            const float e2   = eps * eps;
            const float beta = sk + (dk1 + dk - 2.0f * sk) * et;
            const float alp  = hk * (sk * e2 + dk * et);
            yv[tt] = mask ? xv : (yk + alp / beta);
            const float ome = 1.0f - eps;
            float ld = 2.0f * logf(sk)
                     + logf(dk1 * e2 + 2.0f * sk * et + dk * ome * ome)
                     - 2.0f * logf(beta);
            ldsum += mask ? 0.0f : ld;
        }

        // outputs
        *(float2*)(out + grow + ts) = make_float2(yv[0], yv[1]);
        if (q < 2)
            *(float4*)(out + grow + 8 + q * 4) = *(const float4*)(x + grow + 8 + q * 4);

        ldsum += __shfl_xor_sync(0xffffffffu, ldsum, 1);
        ldsum += __shfl_xor_sync(0xffffffffu, ldsum, 2);
        if (q == 0)
            out[(size_t)B * 16 + row0 + r] = ldsum;
    }
}

extern "C" void kernel_launch(void* const* d_in, const int* in_sizes, int n_in,
                              void* d_out, int out_size) {
    const float* x    = (const float*)d_in[0];
    const float* W0   = (const float*)d_in[1];
    const float* b0   = (const float*)d_in[2];
    const float* W1   = (const float*)d_in[3];
    const float* b1   = (const float*)d_in[4];
    const float* Wout = (const float*)d_in[5];
    const float* bout = (const float*)d_in[6];
    float* out = (float*)d_out;

    const int B = in_sizes[0] / 16;

    prep_w1<<<320, 256>>>(W1);
    prep_wo<<<240, 256>>>(Wout);
    prep_w0<<<40, 256>>>(W0);

    cudaFuncSetAttribute(coupling_hmma_kernel,
                         cudaFuncAttributeMaxDynamicSharedMemorySize, SMEM_BYTES);
    coupling_hmma_kernel<<<B / RB, NT, SMEM_BYTES>>>(x, b0, b1, bout, out, B);
}

// round 10
// speedup vs baseline: 1.8911x; 1.0739x over previous
#include <cuda_runtime.h>
#include <cuda_fp16.h>
#include <math.h>
#include <stdint.h>

#define NT    512
#define RB    128
#define AST   264            // A tile k-stride (fp16): 256 + 8 pad
#define WST   40             // W panel k-stride (fp16): 32 + 8 pad
#define RSTR  193

// ---- smem layout (bytes) ----
#define OFF_A       0                   // 128*264*2 = 67584 fp16
#define OFF_WP      67584               // 3 stages * 20480
#define SLOT_B      20480
#define OFF_A0      108544              // inside WP slot 2: 128*40*2 = 10240
#define OFF_B1S     129024              // 256 f32
#define OFF_BOS     130048              // 192 f32
#define OFF_B0S     130816              // 256 f32
#define OFF_W0P     131840              // 256*40*2 = 20480 (fp16 W0 panel)
#define SMEM_BYTES  152320
// raw buffer (epilogue2): 128*193*4 = 98816 at sm[0], overlaps A+WP (dead then)

#define PAN1_B 20480                    // 256*40*2
#define PAN2_B 15360                    // 192*40*2

// ---- prebuilt fp16 weight panels ----
__device__ __align__(16) __half g_w1[8 * 256 * 40];
__device__ __align__(16) __half g_wo[8 * 192 * 40];
__device__ __align__(16) __half g_w0[256 * 40];     // [W0hi | W0hi | W0lo | 0] k-layout

// ---- helpers ----
__device__ __forceinline__ uint32_t smem_u32(const void* p) {
    uint32_t a;
    asm("{ .reg .u64 t; cvta.to.shared.u64 t, %1; cvt.u32.u64 %0, t; }" : "=r"(a) : "l"(p));
    return a;
}
__device__ __forceinline__ void cp16(uint32_t dst, const void* src) {
    asm volatile("cp.async.cg.shared.global [%0], [%1], 16;" :: "r"(dst), "l"(src));
}
#define CP_COMMIT() asm volatile("cp.async.commit_group;")
#define CP_WAIT0()  asm volatile("cp.async.wait_group 0;")
#define CP_WAIT1()  asm volatile("cp.async.wait_group 1;")

__device__ __forceinline__ void mma16(float* d, uint32_t a0, uint32_t a1, uint32_t a2, uint32_t a3,
                                      uint32_t b0, uint32_t b1) {
    asm volatile("mma.sync.aligned.m16n8k16.row.col.f32.f16.f16.f32 "
                 "{%0,%1,%2,%3}, {%4,%5,%6,%7}, {%8,%9}, {%0,%1,%2,%3};"
                 : "+f"(d[0]), "+f"(d[1]), "+f"(d[2]), "+f"(d[3])
                 : "r"(a0), "r"(a1), "r"(a2), "r"(a3), "r"(b0), "r"(b1));
}
__device__ __forceinline__ void ldsm4(uint32_t& r0, uint32_t& r1, uint32_t& r2, uint32_t& r3,
                                      uint32_t addr) {
    asm volatile("ldmatrix.sync.aligned.m8n8.x4.shared.b16 {%0,%1,%2,%3}, [%4];"
                 : "=r"(r0), "=r"(r1), "=r"(r2), "=r"(r3) : "r"(addr));
}

// ---- fast transcendentals (MUFU-based; error << 1e-4 budget) ----
__device__ __forceinline__ float flog1p(float x) {       // x >= 0
    return (x < 1e-2f) ? x * (1.0f - 0.5f * x) : __logf(1.0f + x);
}
__device__ __forceinline__ float softplusf(float v) {
    return fmaxf(v, 0.0f) + flog1p(__expf(-fabsf(v)));
}

// k-panel compute (K=32) via ldmatrix; 2 m-tiles (32-row warp tile)
template<int NTILES, int ASTRIDE>
__device__ __forceinline__ void panel_compute(uint32_t aLane, uint32_t wLane, float d[2][8][4])
{
    #pragma unroll
    for (int ks = 0; ks < 2; ks++) {
        const uint32_t aK = aLane + ks * 32;      // +16 halves
        const uint32_t wK = wLane + ks * 32;
        uint32_t a[2][4];
        #pragma unroll
        for (int mt = 0; mt < 2; mt++)
            ldsm4(a[mt][0], a[mt][1], a[mt][2], a[mt][3], aK + mt * (16 * ASTRIDE * 2));
        #pragma unroll
        for (int ntp = 0; ntp < NTILES / 2; ntp++) {
            uint32_t b0, b1, b2, b3;
            ldsm4(b0, b1, b2, b3, wK + ntp * (16 * WST * 2));
            #pragma unroll
            for (int mt = 0; mt < 2; mt++) {
                mma16(d[mt][2 * ntp],     a[mt][0], a[mt][1], a[mt][2], a[mt][3], b0, b1);
                mma16(d[mt][2 * ntp + 1], a[mt][0], a[mt][1], a[mt][2], a[mt][3], b2, b3);
            }
        }
    }
}

// ---- prep kernels ----
__global__ void prep_w1(const float* __restrict__ W1) {
    int idx = blockIdx.x * blockDim.x + threadIdx.x;      // 81920
    int p = idx / 10240, rem = idx % 10240;
    int n = rem / 40, kk = rem % 40;
    float w = (kk < 32) ? W1[(p * 32 + kk) * 256 + n] : 0.0f;
    g_w1[idx] = __float2half_rn(w);
}
__global__ void prep_wo(const float* __restrict__ Wout) {
    int idx = blockIdx.x * blockDim.x + threadIdx.x;      // 61440
    int p = idx / 7680, rem = idx % 7680;
    int n = rem / 40, kk = rem % 40;
    float w = (kk < 32 && n < 184) ? Wout[(p * 32 + kk) * 184 + n] : 0.0f;
    g_wo[idx] = __float2half_rn(w);
}
__global__ void prep_w0(const float* __restrict__ W0) {
    int idx = blockIdx.x * blockDim.x + threadIdx.x;      // 10240
    int n = idx / 40, kk = idx % 40;
    __half v = __float2half_rn(0.0f);
    if (kk < 16) {                       // W0hi (k 0..7 for x2hi, 8..15 for x2lo)
        float w = W0[(kk & 7) * 256 + n];
        v = __float2half_rn(w);
    } else if (kk < 24) {                // W0lo (k 16..23 vs x2hi)
        float w = W0[(kk - 16) * 256 + n];
        __half h = __float2half_rn(w);
        v = __float2half_rn(w - __half2float(h));
    }
    g_w0[idx] = v;
}

// ---- main kernel ----
__global__ void __launch_bounds__(NT, 1)
coupling_hmma_kernel(const float* __restrict__ x,
                     const float* __restrict__ b0,
                     const float* __restrict__ b1,
                     const float* __restrict__ bout,
                     float* __restrict__ out,
                     int B)
{
    extern __shared__ char sm[];
    const int tid = threadIdx.x;
    const int wid = tid >> 5, lane = tid & 31;
    const int mw = wid & 3, nw = wid >> 2;          // 4 m-warps x 4 n-warps
    const int qr = lane >> 2, qc = (lane & 3) * 2;
    const int row0 = blockIdx.x * RB;
    const uint32_t sm_u32 = smem_u32(sm);
    const uint32_t wp_u32 = sm_u32 + OFF_WP;

    float* b0s = (float*)(sm + OFF_B0S);
    float* b1s = (float*)(sm + OFF_B1S);
    float* bos = (float*)(sm + OFF_BOS);

    // per-lane ldmatrix address components
    const int aRow = (lane & 15);
    const int aKof = (lane >> 4) * 8;
    const int wRow = (lane & 7) + ((lane >> 4) * 8);
    const int wKof = ((lane >> 3) & 1) * 8;
    const uint32_t aLaneA = sm_u32 + OFF_A + (((mw * 32 + aRow) * AST) + aKof) * 2;
    const uint32_t wRel1 = (((nw * 64 + wRow) * WST) + wKof) * 2;   // GEMM1: nbase = nw*64
    const uint32_t wRel2 = (((nw * 48 + wRow) * WST) + wKof) * 2;   // GEMM2: nbase = nw*48

    // ---- prefetch: panel0 (slot0), panel1 (slot1), W0 panel ----
    for (int i = tid; i < PAN1_B / 16; i += NT)
        cp16(wp_u32 + i * 16, (const char*)g_w1 + i * 16);
    CP_COMMIT();
    for (int i = tid; i < PAN1_B / 16; i += NT)
        cp16(wp_u32 + SLOT_B + i * 16, (const char*)g_w1 + PAN1_B + i * 16);
    CP_COMMIT();
    {
        const uint32_t w0p = sm_u32 + OFF_W0P;
        for (int i = tid; i < 1280; i += NT)
            cp16(w0p + i * 16, (const char*)g_w0 + i * 16);
    }
    CP_COMMIT();

    // ---- consts + A0 staging (exact hi/lo split of x2) ----
    for (int i = tid; i < 256; i += NT) { b0s[i] = b0[i]; b1s[i] = b1[i]; }
    for (int i = tid; i < 192; i += NT) bos[i] = (i < 184) ? bout[i] : 0.0f;
    if (tid < RB) {
        const float4* xp = (const float4*)(x + (size_t)(row0 + tid) * 16);
        float4 xc = xp[2], xd = xp[3];
        float xv[8] = {xc.x, xc.y, xc.z, xc.w, xd.x, xd.y, xd.z, xd.w};
        __half2* a0 = (__half2*)(sm + OFF_A0 + tid * 40 * 2);
        #pragma unroll
        for (int j = 0; j < 8; j += 2) {
            __half h0 = __float2half_rn(xv[j]);
            __half h1 = __float2half_rn(xv[j + 1]);
            __half l0 = __float2half_rn(xv[j] - __half2float(h0));
            __half l1 = __float2half_rn(xv[j + 1] - __half2float(h1));
            a0[j / 2]      = __half2(h0, h1);   // k 0..7  : x2hi
            a0[4 + j / 2]  = __half2(l0, l1);   // k 8..15 : x2lo
            a0[8 + j / 2]  = __half2(h0, h1);   // k 16..23: x2hi (vs W0lo)
            a0[12 + j / 2] = __half2(__float2half_rn(0.f), __float2half_rn(0.f));
            a0[16 + j / 2] = __half2(__float2half_rn(0.f), __float2half_rn(0.f));
        }
    }
    CP_WAIT0();
    __syncthreads();

    float d[2][8][4];
    #pragma unroll
    for (int mt = 0; mt < 2; mt++)
        #pragma unroll
        for (int nt = 0; nt < 8; nt++)
            #pragma unroll
            for (int i = 0; i < 4; i++) d[mt][nt][i] = 0.0f;

    // ---- GEMM0 on tensor pipe (K=32, exact 3-term hi/lo) ----
    {
        const uint32_t aLane0 = sm_u32 + OFF_A0 + (((mw * 32 + aRow) * 40) + aKof) * 2;
        const uint32_t wLane0 = sm_u32 + OFF_W0P + wRel1;
        panel_compute<8, 40>(aLane0, wLane0, d);
    }
    __syncthreads();   // A0 (slot2) reads done before slot2 reused at p=0's issue

    // ---- epilogue0: h0 = relu(d + b0) -> fp16 A tile ----
    #pragma unroll
    for (int mt = 0; mt < 2; mt++) {
        const int r0 = mw * 32 + mt * 16 + qr;
        #pragma unroll
        for (int nt = 0; nt < 8; nt++) {
            const int c = nw * 64 + nt * 8 + qc;
            const float g0 = b0s[c], g1 = b0s[c + 1];
            float v00 = fmaxf(d[mt][nt][0] + g0, 0.f);
            float v01 = fmaxf(d[mt][nt][1] + g1, 0.f);
            float v10 = fmaxf(d[mt][nt][2] + g0, 0.f);
            float v11 = fmaxf(d[mt][nt][3] + g1, 0.f);
            *(__half2*)(sm + OFF_A + ((size_t)r0 * AST + c) * 2) = __floats2half2_rn(v00, v01);
            *(__half2*)(sm + OFF_A + ((size_t)(r0 + 8) * AST + c) * 2) = __floats2half2_rn(v10, v11);
            #pragma unroll
            for (int i = 0; i < 4; i++) d[mt][nt][i] = 0.0f;
        }
    }
    __syncthreads();

    // ---- panel pipeline: p 0..7 = GEMM1 (W1), p 8..15 = GEMM2 (Wout) ----
    for (int p = 0; p < 16; p++) {
        CP_WAIT1();
        __syncthreads();

        if (p == 8) {
            // epilogue1: h1 = relu(d + b1) -> fp16 A tile
            #pragma unroll
            for (int mt = 0; mt < 2; mt++) {
                const int r0 = mw * 32 + mt * 16 + qr;
                #pragma unroll
                for (int nt = 0; nt < 8; nt++) {
                    const int c = nw * 64 + nt * 8 + qc;
                    const float g0 = b1s[c], g1 = b1s[c + 1];
                    float v00 = fmaxf(d[mt][nt][0] + g0, 0.f);
                    float v01 = fmaxf(d[mt][nt][1] + g1, 0.f);
                    float v10 = fmaxf(d[mt][nt][2] + g0, 0.f);
                    float v11 = fmaxf(d[mt][nt][3] + g1, 0.f);
                    *(__half2*)(sm + OFF_A + ((size_t)r0 * AST + c) * 2) = __floats2half2_rn(v00, v01);
                    *(__half2*)(sm + OFF_A + ((size_t)(r0 + 8) * AST + c) * 2) = __floats2half2_rn(v10, v11);
                    #pragma unroll
                    for (int i = 0; i < 4; i++) d[mt][nt][i] = 0.0f;
                }
            }
            __syncthreads();
        }

        // issue panel p+2 into slot (p+2)%3
        if (p + 2 < 16) {
            const int np = p + 2;
            uint32_t dst = wp_u32 + (np % 3) * SLOT_B;
            if (np < 8) {
                const char* src = (const char*)g_w1 + (size_t)np * PAN1_B;
                for (int i = tid; i < PAN1_B / 16; i += NT) cp16(dst + i * 16, src + i * 16);
            } else {
                const char* src = (const char*)g_wo + (size_t)(np - 8) * PAN2_B;
                for (int i = tid; i < PAN2_B / 16; i += NT) cp16(dst + i * 16, src + i * 16);
            }
        }
        CP_COMMIT();

        const uint32_t slot = wp_u32 + (p % 3) * SLOT_B;
        if (p < 8)
            panel_compute<8, AST>(aLaneA + p * 64, slot + wRel1, d);          // akbase = p*32 halves
        else
            panel_compute<6, AST>(aLaneA + (p - 8) * 64, slot + wRel2, d);
    }
    __syncthreads();   // all GEMM2 A/W reads done

    // ---- epilogue2: raw = d + bout -> smem f32 [128][193] (overlaps A+WP) ----
    float* rawS = (float*)sm;
    #pragma unroll
    for (int mt = 0; mt < 2; mt++) {
        const int r0 = mw * 32 + mt * 16 + qr;
        #pragma unroll
        for (int nt = 0; nt < 6; nt++) {
            const int c = nw * 48 + nt * 8 + qc;
            rawS[r0 * RSTR + c]           = d[mt][nt][0] + bos[c];
            rawS[r0 * RSTR + c + 1]       = d[mt][nt][1] + bos[c + 1];
            rawS[(r0 + 8) * RSTR + c]     = d[mt][nt][2] + bos[c];
            rawS[(r0 + 8) * RSTR + c + 1] = d[mt][nt][3] + bos[c + 1];
        }
    }
    __syncthreads();

    // ---- spline: 4 threads/row, 2 transforms each (fast-math MUFU path) ----
    {
        const int r = tid >> 2;
        const int q = tid & 3;
        const int ts = q * 2;
        const size_t grow = (size_t)(row0 + r) * 16;
        const float2 x1p = *(const float2*)(x + grow + ts);
        const float x1v[2] = {x1p.x, x1p.y};
        const float CNST = logf(expf(1.0f - 1e-4f) - 1.0f);
        float yv[2];
        float ldsum = 0.0f;

        #pragma unroll
        for (int tt = 0; tt < 2; tt++) {
            const float* raw = rawS + r * RSTR + (ts + tt) * 23;
            const float xv = x1v[tt];

            float rw[8], rh[8];
            #pragma unroll
            for (int c = 0; c < 8; c++) { rw[c] = raw[c]; rh[c] = raw[8 + c]; }

            float m = rw[0];
            #pragma unroll
            for (int c = 1; c < 8; c++) m = fmaxf(m, rw[c]);
            float sum = 0.0f, ew[8];
            #pragma unroll
            for (int c = 0; c < 8; c++) { ew[c] = __expf(rw[c] - m); sum += ew[c]; }
            float inv = __fdividef(1.0f, sum);
            float wdt[8];
            #pragma unroll
            for (int c = 0; c < 8; c++) wdt[c] = 2.0f * (1e-4f + (1.0f - 8e-4f) * ew[c] * inv);

            m = rh[0];
            #pragma unroll
            for (int c = 1; c < 8; c++) m = fmaxf(m, rh[c]);
            sum = 0.0f;
            #pragma unroll
            for (int c = 0; c < 8; c++) { ew[c] = __expf(rh[c] - m); sum += ew[c]; }
            inv = __fdividef(1.0f, sum);
            float hgt[8];
            #pragma unroll
            for (int c = 0; c < 8; c++) hgt[c] = 2.0f * (1e-4f + (1.0f - 8e-4f) * ew[c] * inv);

            float dv[9];
            dv[0] = 1.0f; dv[8] = 1.0f;
            #pragma unroll
            for (int c = 0; c < 7; c++) dv[c + 1] = softplusf(raw[16 + c] + CNST) + 1e-4f;

            const bool mask = (xv <= -0.999f) || (xv >= 0.999f);
            const float xin = mask ? 0.0f : xv;

            float cx = -1.0f, cy = -1.0f;
            float xk = -1.0f, yk = -1.0f, wk = wdt[0], hk = hgt[0], dk = dv[0], dk1 = dv[1];
            #pragma unroll
            for (int i = 0; i < 8; i++) {
                if (cx <= xin) { xk = cx; yk = cy; wk = wdt[i]; hk = hgt[i]; dk = dv[i]; dk1 = dv[i + 1]; }
                cx += wdt[i]; cy += hgt[i];
            }

            const float invwk = __fdividef(1.0f, wk);
            const float sk   = hk * invwk;
            const float eps  = (xin - xk) * invwk;
            const float et   = eps * (1.0f - eps);
            const float e2   = eps * eps;
            const float beta = sk + (dk1 + dk - 2.0f * sk) * et;
            const float alp  = hk * (sk * e2 + dk * et);
            yv[tt] = mask ? xv : (yk + __fdividef(alp, beta));
            const float ome = 1.0f - eps;
            float ld = 2.0f * __logf(sk)
                     + __logf(dk1 * e2 + 2.0f * sk * et + dk * ome * ome)
                     - 2.0f * __logf(beta);
            ldsum += mask ? 0.0f : ld;
        }

        // outputs
        *(float2*)(out + grow + ts) = make_float2(yv[0], yv[1]);
        if (q < 2)
            *(float4*)(out + grow + 8 + q * 4) = *(const float4*)(x + grow + 8 + q * 4);

        ldsum += __shfl_xor_sync(0xffffffffu, ldsum, 1);
        ldsum += __shfl_xor_sync(0xffffffffu, ldsum, 2);
        if (q == 0)
            out[(size_t)B * 16 + row0 + r] = ldsum;
    }
}

extern "C" void kernel_launch(void* const* d_in, const int* in_sizes, int n_in,
                              void* d_out, int out_size) {
    const float* x    = (const float*)d_in[0];
    const float* W0   = (const float*)d_in[1];
    const float* b0   = (const float*)d_in[2];
    const float* W1   = (const float*)d_in[3];
    const float* b1   = (const float*)d_in[4];
    const float* Wout = (const float*)d_in[5];
    const float* bout = (const float*)d_in[6];
    float* out = (float*)d_out;

    const int B = in_sizes[0] / 16;

    prep_w1<<<320, 256>>>(W1);
    prep_wo<<<240, 256>>>(Wout);
    prep_w0<<<40, 256>>>(W0);

    cudaFuncSetAttribute(coupling_hmma_kernel,
                         cudaFuncAttributeMaxDynamicSharedMemorySize, SMEM_BYTES);
    coupling_hmma_kernel<<<B / RB, NT, SMEM_BYTES>>>(x, b0, b1, bout, out, B);
}

// round 11
// speedup vs baseline: 2.0527x; 1.0855x over previous
#include <cuda_runtime.h>
#include <cuda_fp16.h>
#include <math.h>
#include <stdint.h>

#define NT    512
#define RB    128
#define AST   264            // A tile k-stride (fp16): 256 + 8 pad
#define WST   40             // W panel k-stride (fp16): 32 + 8 pad
#define RSTR  193

// ---- smem layout (bytes) ----
#define OFF_A       0                   // 128*264*2 = 67584 fp16
#define OFF_WP      67584               // 3 stage slots * 40960
#define SLOT_B      40960               // one stage = 2 K=32 panels
#define OFF_A0      149504              // inside slot 2: 128*40*2 = 10240
#define OFF_W0P     159744              // inside slot 2: 256*40*2 = 20480
#define OFF_B1S     190464              // 256 f32
#define OFF_BOS     191488              // 192 f32
#define OFF_B0S     192256              // 256 f32
#define SMEM_BYTES  193280
// raw buffer (epilogue2): 128*193*4 = 98816 at sm[0], overlaps A+slot0 (dead then)

#define PAN1_B 20480                    // 256*40*2 (one K=32 GEMM1 panel)
#define PAN2_B 15360                    // 192*40*2
#define STG1_B 40960                    // GEMM1 stage (2 panels)
#define STG2_B 30720                    // GEMM2 stage (2 panels)

// ---- prebuilt fp16 weight panels ----
__device__ __align__(16) __half g_w1[8 * 256 * 40];
__device__ __align__(16) __half g_wo[8 * 192 * 40];
__device__ __align__(16) __half g_w0[256 * 40];     // [W0hi | W0hi | W0lo | 0] k-layout

// ---- helpers ----
__device__ __forceinline__ uint32_t smem_u32(const void* p) {
    uint32_t a;
    asm("{ .reg .u64 t; cvta.to.shared.u64 t, %1; cvt.u32.u64 %0, t; }" : "=r"(a) : "l"(p));
    return a;
}
__device__ __forceinline__ void cp16(uint32_t dst, const void* src) {
    asm volatile("cp.async.cg.shared.global [%0], [%1], 16;" :: "r"(dst), "l"(src));
}
#define CP_COMMIT() asm volatile("cp.async.commit_group;")
#define CP_WAIT0()  asm volatile("cp.async.wait_group 0;")
#define CP_WAIT1()  asm volatile("cp.async.wait_group 1;")

__device__ __forceinline__ void mma16(float* d, uint32_t a0, uint32_t a1, uint32_t a2, uint32_t a3,
                                      uint32_t b0, uint32_t b1) {
    asm volatile("mma.sync.aligned.m16n8k16.row.col.f32.f16.f16.f32 "
                 "{%0,%1,%2,%3}, {%4,%5,%6,%7}, {%8,%9}, {%0,%1,%2,%3};"
                 : "+f"(d[0]), "+f"(d[1]), "+f"(d[2]), "+f"(d[3])
                 : "r"(a0), "r"(a1), "r"(a2), "r"(a3), "r"(b0), "r"(b1));
}
__device__ __forceinline__ void ldsm4(uint32_t& r0, uint32_t& r1, uint32_t& r2, uint32_t& r3,
                                      uint32_t addr) {
    asm volatile("ldmatrix.sync.aligned.m8n8.x4.shared.b16 {%0,%1,%2,%3}, [%4];"
                 : "=r"(r0), "=r"(r1), "=r"(r2), "=r"(r3) : "r"(addr));
}

// ---- fast transcendentals (MUFU-based; error << 1e-4 budget) ----
__device__ __forceinline__ float flog1p(float x) {       // x >= 0
    return (x < 1e-2f) ? x * (1.0f - 0.5f * x) : __logf(1.0f + x);
}
__device__ __forceinline__ float softplusf(float v) {
    return fmaxf(v, 0.0f) + flog1p(__expf(-fabsf(v)));
}

// k-panel compute (K=32) via ldmatrix; 2 m-tiles (32-row warp tile)
template<int NTILES, int ASTRIDE>
__device__ __forceinline__ void panel_compute(uint32_t aLane, uint32_t wLane, float d[2][8][4])
{
    #pragma unroll
    for (int ks = 0; ks < 2; ks++) {
        const uint32_t aK = aLane + ks * 32;      // +16 halves
        const uint32_t wK = wLane + ks * 32;
        uint32_t a[2][4];
        #pragma unroll
        for (int mt = 0; mt < 2; mt++)
            ldsm4(a[mt][0], a[mt][1], a[mt][2], a[mt][3], aK + mt * (16 * ASTRIDE * 2));
        #pragma unroll
        for (int ntp = 0; ntp < NTILES / 2; ntp++) {
            uint32_t b0, b1, b2, b3;
            ldsm4(b0, b1, b2, b3, wK + ntp * (16 * WST * 2));
            #pragma unroll
            for (int mt = 0; mt < 2; mt++) {
                mma16(d[mt][2 * ntp],     a[mt][0], a[mt][1], a[mt][2], a[mt][3], b0, b1);
                mma16(d[mt][2 * ntp + 1], a[mt][0], a[mt][1], a[mt][2], a[mt][3], b2, b3);
            }
        }
    }
}

// ---- prep kernels ----
__global__ void prep_w1(const float* __restrict__ W1) {
    int idx = blockIdx.x * blockDim.x + threadIdx.x;      // 81920
    int p = idx / 10240, rem = idx % 10240;
    int n = rem / 40, kk = rem % 40;
    float w = (kk < 32) ? W1[(p * 32 + kk) * 256 + n] : 0.0f;
    g_w1[idx] = __float2half_rn(w);
}
__global__ void prep_wo(const float* __restrict__ Wout) {
    int idx = blockIdx.x * blockDim.x + threadIdx.x;      // 61440
    int p = idx / 7680, rem = idx % 7680;
    int n = rem / 40, kk = rem % 40;
    float w = (kk < 32 && n < 184) ? Wout[(p * 32 + kk) * 184 + n] : 0.0f;
    g_wo[idx] = __float2half_rn(w);
}
__global__ void prep_w0(const float* __restrict__ W0) {
    int idx = blockIdx.x * blockDim.x + threadIdx.x;      // 10240
    int n = idx / 40, kk = idx % 40;
    __half v = __float2half_rn(0.0f);
    if (kk < 16) {                       // W0hi (k 0..7 for x2hi, 8..15 for x2lo)
        float w = W0[(kk & 7) * 256 + n];
        v = __float2half_rn(w);
    } else if (kk < 24) {                // W0lo (k 16..23 vs x2hi)
        float w = W0[(kk - 16) * 256 + n];
        __half h = __float2half_rn(w);
        v = __float2half_rn(w - __half2float(h));
    }
    g_w0[idx] = v;
}

// ---- main kernel ----
__global__ void __launch_bounds__(NT, 1)
coupling_hmma_kernel(const float* __restrict__ x,
                     const float* __restrict__ b0,
                     const float* __restrict__ b1,
                     const float* __restrict__ bout,
                     float* __restrict__ out,
                     int B)
{
    extern __shared__ char sm[];
    const int tid = threadIdx.x;
    const int wid = tid >> 5, lane = tid & 31;
    const int mw = wid & 3, nw = wid >> 2;          // 4 m-warps x 4 n-warps
    const int qr = lane >> 2, qc = (lane & 3) * 2;
    const int row0 = blockIdx.x * RB;
    const uint32_t sm_u32 = smem_u32(sm);
    const uint32_t wp_u32 = sm_u32 + OFF_WP;

    float* b0s = (float*)(sm + OFF_B0S);
    float* b1s = (float*)(sm + OFF_B1S);
    float* bos = (float*)(sm + OFF_BOS);

    // per-lane ldmatrix address components
    const int aRow = (lane & 15);
    const int aKof = (lane >> 4) * 8;
    const int wRow = (lane & 7) + ((lane >> 4) * 8);
    const int wKof = ((lane >> 3) & 1) * 8;
    const uint32_t aLaneA = sm_u32 + OFF_A + (((mw * 32 + aRow) * AST) + aKof) * 2;
    const uint32_t wRel1 = (((nw * 64 + wRow) * WST) + wKof) * 2;   // GEMM1: nbase = nw*64
    const uint32_t wRel2 = (((nw * 48 + wRow) * WST) + wKof) * 2;   // GEMM2: nbase = nw*48

    // ---- prefetch: stage0 (slot0), stage1 (slot1), W0 panel (slot2) ----
    for (int i = tid; i < STG1_B / 16; i += NT)
        cp16(wp_u32 + i * 16, (const char*)g_w1 + i * 16);
    CP_COMMIT();
    for (int i = tid; i < STG1_B / 16; i += NT)
        cp16(wp_u32 + SLOT_B + i * 16, (const char*)g_w1 + STG1_B + i * 16);
    CP_COMMIT();
    {
        const uint32_t w0p = sm_u32 + OFF_W0P;
        for (int i = tid; i < 1280; i += NT)
            cp16(w0p + i * 16, (const char*)g_w0 + i * 16);
    }
    CP_COMMIT();

    // ---- consts + A0 staging (exact hi/lo split of x2) ----
    for (int i = tid; i < 256; i += NT) { b0s[i] = b0[i]; b1s[i] = b1[i]; }
    for (int i = tid; i < 192; i += NT) bos[i] = (i < 184) ? bout[i] : 0.0f;
    if (tid < RB) {
        const float4* xp = (const float4*)(x + (size_t)(row0 + tid) * 16);
        float4 xc = xp[2], xd = xp[3];
        float xv[8] = {xc.x, xc.y, xc.z, xc.w, xd.x, xd.y, xd.z, xd.w};
        __half2* a0 = (__half2*)(sm + OFF_A0 + tid * 40 * 2);
        #pragma unroll
        for (int j = 0; j < 8; j += 2) {
            __half h0 = __float2half_rn(xv[j]);
            __half h1 = __float2half_rn(xv[j + 1]);
            __half l0 = __float2half_rn(xv[j] - __half2float(h0));
            __half l1 = __float2half_rn(xv[j + 1] - __half2float(h1));
            a0[j / 2]      = __half2(h0, h1);   // k 0..7  : x2hi
            a0[4 + j / 2]  = __half2(l0, l1);   // k 8..15 : x2lo
            a0[8 + j / 2]  = __half2(h0, h1);   // k 16..23: x2hi (vs W0lo)
            a0[12 + j / 2] = __half2(__float2half_rn(0.f), __float2half_rn(0.f));
            a0[16 + j / 2] = __half2(__float2half_rn(0.f), __float2half_rn(0.f));
        }
    }
    CP_WAIT0();
    __syncthreads();

    float d[2][8][4];
    #pragma unroll
    for (int mt = 0; mt < 2; mt++)
        #pragma unroll
        for (int nt = 0; nt < 8; nt++)
            #pragma unroll
            for (int i = 0; i < 4; i++) d[mt][nt][i] = 0.0f;

    // ---- GEMM0 on tensor pipe (K=32, exact 3-term hi/lo) ----
    {
        const uint32_t aLane0 = sm_u32 + OFF_A0 + (((mw * 32 + aRow) * 40) + aKof) * 2;
        const uint32_t wLane0 = sm_u32 + OFF_W0P + wRel1;
        panel_compute<8, 40>(aLane0, wLane0, d);
    }
    __syncthreads();   // A0/W0P (slot2) reads done before stage 2 lands there

    // ---- epilogue0: h0 = relu(d + b0) -> fp16 A tile ----
    #pragma unroll
    for (int mt = 0; mt < 2; mt++) {
        const int r0 = mw * 32 + mt * 16 + qr;
        #pragma unroll
        for (int nt = 0; nt < 8; nt++) {
            const int c = nw * 64 + nt * 8 + qc;
            const float g0 = b0s[c], g1 = b0s[c + 1];
            float v00 = fmaxf(d[mt][nt][0] + g0, 0.f);
            float v01 = fmaxf(d[mt][nt][1] + g1, 0.f);
            float v10 = fmaxf(d[mt][nt][2] + g0, 0.f);
            float v11 = fmaxf(d[mt][nt][3] + g1, 0.f);
            *(__half2*)(sm + OFF_A + ((size_t)r0 * AST + c) * 2) = __floats2half2_rn(v00, v01);
            *(__half2*)(sm + OFF_A + ((size_t)(r0 + 8) * AST + c) * 2) = __floats2half2_rn(v10, v11);
            #pragma unroll
            for (int i = 0; i < 4; i++) d[mt][nt][i] = 0.0f;
        }
    }
    __syncthreads();

    // ---- stage pipeline: s 0..3 = GEMM1 (panels 2s,2s+1), s 4..7 = GEMM2 ----
    // 3 slots, 2 stages in flight. wait(stage s) -> sync -> [epi1 @s=4] -> issue(s+2) -> compute 2 panels
    for (int s = 0; s < 8; s++) {
        CP_WAIT1();
        __syncthreads();

        if (s == 4) {
            // epilogue1: h1 = relu(d + b1) -> fp16 A tile
            #pragma unroll
            for (int mt = 0; mt < 2; mt++) {
                const int r0 = mw * 32 + mt * 16 + qr;
                #pragma unroll
                for (int nt = 0; nt < 8; nt++) {
                    const int c = nw * 64 + nt * 8 + qc;
                    const float g0 = b1s[c], g1 = b1s[c + 1];
                    float v00 = fmaxf(d[mt][nt][0] + g0, 0.f);
                    float v01 = fmaxf(d[mt][nt][1] + g1, 0.f);
                    float v10 = fmaxf(d[mt][nt][2] + g0, 0.f);
                    float v11 = fmaxf(d[mt][nt][3] + g1, 0.f);
                    *(__half2*)(sm + OFF_A + ((size_t)r0 * AST + c) * 2) = __floats2half2_rn(v00, v01);
                    *(__half2*)(sm + OFF_A + ((size_t)(r0 + 8) * AST + c) * 2) = __floats2half2_rn(v10, v11);
                    #pragma unroll
                    for (int i = 0; i < 4; i++) d[mt][nt][i] = 0.0f;
                }
            }
            __syncthreads();
        }

        // issue stage s+2 into slot (s+2)%3 (its occupant s-1 consumed last iter)
        if (s + 2 < 8) {
            const int ns = s + 2;
            uint32_t dst = wp_u32 + (ns % 3) * SLOT_B;
            if (ns < 4) {
                const char* src = (const char*)g_w1 + (size_t)ns * STG1_B;
                for (int i = tid; i < STG1_B / 16; i += NT) cp16(dst + i * 16, src + i * 16);
            } else {
                const char* src = (const char*)g_wo + (size_t)(ns - 4) * STG2_B;
                for (int i = tid; i < STG2_B / 16; i += NT) cp16(dst + i * 16, src + i * 16);
            }
        }
        CP_COMMIT();

        const uint32_t slot = wp_u32 + (s % 3) * SLOT_B;
        if (s < 4) {
            panel_compute<8, AST>(aLaneA + (2 * s) * 64,     slot + wRel1, d);
            panel_compute<8, AST>(aLaneA + (2 * s + 1) * 64, slot + PAN1_B + wRel1, d);
        } else {
            panel_compute<6, AST>(aLaneA + (2 * s - 8) * 64, slot + wRel2, d);
            panel_compute<6, AST>(aLaneA + (2 * s - 7) * 64, slot + PAN2_B + wRel2, d);
        }
    }
    __syncthreads();   // all GEMM2 A/W reads done

    // ---- epilogue2: raw = d + bout -> smem f32 [128][193] (overlaps A+slot0) ----
    float* rawS = (float*)sm;
    #pragma unroll
    for (int mt = 0; mt < 2; mt++) {
        const int r0 = mw * 32 + mt * 16 + qr;
        #pragma unroll
        for (int nt = 0; nt < 6; nt++) {
            const int c = nw * 48 + nt * 8 + qc;
            rawS[r0 * RSTR + c]           = d[mt][nt][0] + bos[c];
            rawS[r0 * RSTR + c + 1]       = d[mt][nt][1] + bos[c + 1];
            rawS[(r0 + 8) * RSTR + c]     = d[mt][nt][2] + bos[c];
            rawS[(r0 + 8) * RSTR + c + 1] = d[mt][nt][3] + bos[c + 1];
        }
    }
    __syncthreads();

    // ---- spline: 4 threads/row, 2 transforms each (fast-math MUFU path) ----
    {
        const int r = tid >> 2;
        const int q = tid & 3;
        const int ts = q * 2;
        const size_t grow = (size_t)(row0 + r) * 16;
        const float2 x1p = *(const float2*)(x + grow + ts);
        const float x1v[2] = {x1p.x, x1p.y};
        const float CNST = logf(expf(1.0f - 1e-4f) - 1.0f);
        float yv[2];
        float ldsum = 0.0f;

        #pragma unroll
        for (int tt = 0; tt < 2; tt++) {
            const float* raw = rawS + r * RSTR + (ts + tt) * 23;
            const float xv = x1v[tt];

            float rw[8], rh[8];
            #pragma unroll
            for (int c = 0; c < 8; c++) { rw[c] = raw[c]; rh[c] = raw[8 + c]; }

            float m = rw[0];
            #pragma unroll
            for (int c = 1; c < 8; c++) m = fmaxf(m, rw[c]);
            float sum = 0.0f, ew[8];
            #pragma unroll
            for (int c = 0; c < 8; c++) { ew[c] = __expf(rw[c] - m); sum += ew[c]; }
            float inv = __fdividef(1.0f, sum);
            float wdt[8];
            #pragma unroll
            for (int c = 0; c < 8; c++) wdt[c] = 2.0f * (1e-4f + (1.0f - 8e-4f) * ew[c] * inv);

            m = rh[0];
            #pragma unroll
            for (int c = 1; c < 8; c++) m = fmaxf(m, rh[c]);
            sum = 0.0f;
            #pragma unroll
            for (int c = 0; c < 8; c++) { ew[c] = __expf(rh[c] - m); sum += ew[c]; }
            inv = __fdividef(1.0f, sum);
            float hgt[8];
            #pragma unroll
            for (int c = 0; c < 8; c++) hgt[c] = 2.0f * (1e-4f + (1.0f - 8e-4f) * ew[c] * inv);

            float dv[9];
            dv[0] = 1.0f; dv[8] = 1.0f;
            #pragma unroll
            for (int c = 0; c < 7; c++) dv[c + 1] = softplusf(raw[16 + c] + CNST) + 1e-4f;

            const bool mask = (xv <= -0.999f) || (xv >= 0.999f);
            const float xin = mask ? 0.0f : xv;

            float cx = -1.0f, cy = -1.0f;
            float xk = -1.0f, yk = -1.0f, wk = wdt[0], hk = hgt[0], dk = dv[0], dk1 = dv[1];
            #pragma unroll
            for (int i = 0; i < 8; i++) {
                if (cx <= xin) { xk = cx; yk = cy; wk = wdt[i]; hk = hgt[i]; dk = dv[i]; dk1 = dv[i + 1]; }
                cx += wdt[i]; cy += hgt[i];
            }

            const float invwk = __fdividef(1.0f, wk);
            const float sk   = hk * invwk;
            const float eps  = (xin - xk) * invwk;
            const float et   = eps * (1.0f - eps);
            const float e2   = eps * eps;
            const float beta = sk + (dk1 + dk - 2.0f * sk) * et;
            const float alp  = hk * (sk * e2 + dk * et);
            yv[tt] = mask ? xv : (yk + __fdividef(alp, beta));
            const float ome = 1.0f - eps;
            float ld = 2.0f * __logf(sk)
                     + __logf(dk1 * e2 + 2.0f * sk * et + dk * ome * ome)
                     - 2.0f * __logf(beta);
            ldsum += mask ? 0.0f : ld;
        }

        // outputs
        *(float2*)(out + grow + ts) = make_float2(yv[0], yv[1]);
        if (q < 2)
            *(float4*)(out + grow + 8 + q * 4) = *(const float4*)(x + grow + 8 + q * 4);

        ldsum += __shfl_xor_sync(0xffffffffu, ldsum, 1);
        ldsum += __shfl_xor_sync(0xffffffffu, ldsum, 2);
        if (q == 0)
            out[(size_t)B * 16 + row0 + r] = ldsum;
    }
}

extern "C" void kernel_launch(void* const* d_in, const int* in_sizes, int n_in,
                              void* d_out, int out_size) {
    const float* x    = (const float*)d_in[0];
    const float* W0   = (const float*)d_in[1];
    const float* b0   = (const float*)d_in[2];
    const float* W1   = (const float*)d_in[3];
    const float* b1   = (const float*)d_in[4];
    const float* Wout = (const float*)d_in[5];
    const float* bout = (const float*)d_in[6];
    float* out = (float*)d_out;

    const int B = in_sizes[0] / 16;

    prep_w1<<<320, 256>>>(W1);
    prep_wo<<<240, 256>>>(Wout);
    prep_w0<<<40, 256>>>(W0);

    cudaFuncSetAttribute(coupling_hmma_kernel,
                         cudaFuncAttributeMaxDynamicSharedMemorySize, SMEM_BYTES);
    coupling_hmma_kernel<<<B / RB, NT, SMEM_BYTES>>>(x, b0, b1, bout, out, B);
}